// round 1
// baseline (speedup 1.0000x reference)
#include <cuda_runtime.h>
#include <math.h>

#define B_ 2
#define S_ 2048
#define D_ 1024
#define H_ 16
#define HD_ 64

// Scratch (allocation-free rule: __device__ globals)
__device__ float g_q[B_ * S_ * D_];
__device__ float g_k[B_ * S_ * D_];
__device__ float g_v[B_ * S_ * D_];
__device__ float g_att[B_ * S_ * D_];

// ---------------------------------------------------------------------------
// SGEMM: C[M,N] = A[M,K] @ W[K,N] + bias
// 128x128 block tile, BK=8, 256 threads, 8x8 micro-tile per thread.
// SCATTER=1 writes output in [B,H,S,HD] head layout instead of [M,N].
// ---------------------------------------------------------------------------
template <int SCATTER>
__global__ __launch_bounds__(256) void sgemm_kernel(
    const float* __restrict__ A, const float* __restrict__ W,
    const float* __restrict__ bias, float* __restrict__ C,
    int M, int N, int K)
{
    __shared__ float As[8][128];   // transposed: As[k][m]
    __shared__ float Bs[8][128];   // Bs[k][n]

    const int tid = threadIdx.x;
    const int tx = tid & 15;
    const int ty = tid >> 4;
    const int m0 = blockIdx.y * 128;
    const int n0 = blockIdx.x * 128;

    float acc[8][8];
#pragma unroll
    for (int i = 0; i < 8; i++)
#pragma unroll
        for (int j = 0; j < 8; j++) acc[i][j] = 0.0f;

    const int ar = tid >> 1;          // 0..127
    const int ac = (tid & 1) * 4;     // 0 or 4
    const int br = tid >> 5;          // 0..7
    const int bc = (tid & 31) * 4;    // 0..124

    const float* Aptr = A + (size_t)(m0 + ar) * K + ac;
    const float* Wptr = W + (size_t)br * N + n0 + bc;

    for (int kt = 0; kt < K; kt += 8) {
        float4 av = *(const float4*)(Aptr + kt);
        float4 bv = *(const float4*)(Wptr + (size_t)kt * N);
        __syncthreads();
        As[ac + 0][ar] = av.x;
        As[ac + 1][ar] = av.y;
        As[ac + 2][ar] = av.z;
        As[ac + 3][ar] = av.w;
        *(float4*)&Bs[br][bc] = bv;
        __syncthreads();

#pragma unroll
        for (int kk = 0; kk < 8; kk++) {
            float a[8], b[8];
            *(float4*)&a[0] = *(const float4*)&As[kk][ty * 8];
            *(float4*)&a[4] = *(const float4*)&As[kk][ty * 8 + 4];
            *(float4*)&b[0] = *(const float4*)&Bs[kk][tx * 8];
            *(float4*)&b[4] = *(const float4*)&Bs[kk][tx * 8 + 4];
#pragma unroll
            for (int i = 0; i < 8; i++)
#pragma unroll
                for (int j = 0; j < 8; j++)
                    acc[i][j] = fmaf(a[i], b[j], acc[i][j]);
        }
    }

#pragma unroll
    for (int i = 0; i < 8; i++) {
        const int m = m0 + ty * 8 + i;
#pragma unroll
        for (int j = 0; j < 8; j++) {
            const int n = n0 + tx * 8 + j;
            const float v = acc[i][j] + bias[n];
            if (SCATTER) {
                const int bb = m >> 11;          // m / S_
                const int s  = m & (S_ - 1);
                const int h  = n >> 6;           // n / HD_
                const int d  = n & (HD_ - 1);
                C[((size_t)(bb * H_ + h) * S_ + s) * HD_ + d] = v;
            } else {
                C[(size_t)m * N + n] = v;
            }
        }
    }
}

// ---------------------------------------------------------------------------
// Flash attention: one CTA = one (b,h) x 64-query tile. 256 threads (16x16),
// 4x4 micro-tiles for both QK^T and PV 64x64x64 GEMMs. Online softmax with
// 16-lane shfl reductions. Writes [B,S,D] (heads re-merged).
// ---------------------------------------------------------------------------
#define QS_STRIDE 68
#define KS_STRIDE 65
#define VS_STRIDE 68
#define PS_STRIDE 68
#define FLASH_SMEM_FLOATS (64 * QS_STRIDE + 64 * KS_STRIDE + 64 * VS_STRIDE + 64 * PS_STRIDE)

__global__ __launch_bounds__(256) void flash_kernel(
    const float* __restrict__ Q, const float* __restrict__ K,
    const float* __restrict__ V, float* __restrict__ Oout)
{
    extern __shared__ float sm[];
    float* Qs = sm;                     // [d][r] transposed, stride 68
    float* Ks = Qs + 64 * QS_STRIDE;    // [j][d], stride 65
    float* Vs = Ks + 64 * KS_STRIDE;    // [j][d], stride 68
    float* Ps = Vs + 64 * VS_STRIDE;    // [j][r] (P transposed), stride 68

    const int tid = threadIdx.x;
    const int tx = tid & 15;
    const int ty = tid >> 4;
    const int q0 = blockIdx.x * 64;
    const int bh = blockIdx.y;          // b*H + h

    const float* Qb = Q + (size_t)bh * S_ * HD_;
    const float* Kb = K + (size_t)bh * S_ * HD_;
    const float* Vb = V + (size_t)bh * S_ * HD_;

    const float scale = 0.125f;  // 1/sqrt(64)

    // Load Q tile (pre-scaled), store transposed Qs[d][r]
    {
        const int r0 = tid >> 4;            // 0..15
        const int d4 = (tid & 15) * 4;      // 0..60
#pragma unroll
        for (int it = 0; it < 4; it++) {
            const int r = r0 + it * 16;
            float4 qv = *(const float4*)&Qb[(size_t)(q0 + r) * HD_ + d4];
            Qs[(d4 + 0) * QS_STRIDE + r] = qv.x * scale;
            Qs[(d4 + 1) * QS_STRIDE + r] = qv.y * scale;
            Qs[(d4 + 2) * QS_STRIDE + r] = qv.z * scale;
            Qs[(d4 + 3) * QS_STRIDE + r] = qv.w * scale;
        }
    }

    float o[4][4];
    float mrow[4], lrow[4];
#pragma unroll
    for (int i = 0; i < 4; i++) {
        mrow[i] = -INFINITY;
        lrow[i] = 0.0f;
#pragma unroll
        for (int j = 0; j < 4; j++) o[i][j] = 0.0f;
    }

    for (int kt = 0; kt < S_; kt += 64) {
        __syncthreads();  // protect Qs (first iter) / Ps,Vs (later) before overwrite
        // Load K and V tiles
        {
            const int r0 = tid >> 4;
            const int d4 = (tid & 15) * 4;
#pragma unroll
            for (int it = 0; it < 4; it++) {
                const int j = r0 + it * 16;
                float4 kv = *(const float4*)&Kb[(size_t)(kt + j) * HD_ + d4];
                Ks[j * KS_STRIDE + d4 + 0] = kv.x;
                Ks[j * KS_STRIDE + d4 + 1] = kv.y;
                Ks[j * KS_STRIDE + d4 + 2] = kv.z;
                Ks[j * KS_STRIDE + d4 + 3] = kv.w;
                float4 vv = *(const float4*)&Vb[(size_t)(kt + j) * HD_ + d4];
                *(float4*)&Vs[j * VS_STRIDE + d4] = vv;
            }
        }
        __syncthreads();

        // S = Q @ K^T (Q pre-scaled)
        float s[4][4];
#pragma unroll
        for (int i = 0; i < 4; i++)
#pragma unroll
            for (int j = 0; j < 4; j++) s[i][j] = 0.0f;

#pragma unroll 4
        for (int d = 0; d < 64; d++) {
            float a[4];
            *(float4*)&a[0] = *(const float4*)&Qs[d * QS_STRIDE + ty * 4];
            float b[4];
            b[0] = Ks[(tx * 4 + 0) * KS_STRIDE + d];
            b[1] = Ks[(tx * 4 + 1) * KS_STRIDE + d];
            b[2] = Ks[(tx * 4 + 2) * KS_STRIDE + d];
            b[3] = Ks[(tx * 4 + 3) * KS_STRIDE + d];
#pragma unroll
            for (int i = 0; i < 4; i++)
#pragma unroll
                for (int j = 0; j < 4; j++)
                    s[i][j] = fmaf(a[i], b[j], s[i][j]);
        }

        // Online softmax update (row groups = 16 consecutive lanes)
#pragma unroll
        for (int i = 0; i < 4; i++) {
            float tm = fmaxf(fmaxf(s[i][0], s[i][1]), fmaxf(s[i][2], s[i][3]));
            tm = fmaxf(tm, __shfl_xor_sync(0xffffffffu, tm, 8));
            tm = fmaxf(tm, __shfl_xor_sync(0xffffffffu, tm, 4));
            tm = fmaxf(tm, __shfl_xor_sync(0xffffffffu, tm, 2));
            tm = fmaxf(tm, __shfl_xor_sync(0xffffffffu, tm, 1));
            const float mn = fmaxf(mrow[i], tm);
            const float alpha = __expf(mrow[i] - mn);
            mrow[i] = mn;
            float rs = 0.0f;
#pragma unroll
            for (int j = 0; j < 4; j++) {
                const float p = __expf(s[i][j] - mn);
                s[i][j] = p;
                rs += p;
            }
            rs += __shfl_xor_sync(0xffffffffu, rs, 8);
            rs += __shfl_xor_sync(0xffffffffu, rs, 4);
            rs += __shfl_xor_sync(0xffffffffu, rs, 2);
            rs += __shfl_xor_sync(0xffffffffu, rs, 1);
            lrow[i] = lrow[i] * alpha + rs;
#pragma unroll
            for (int j = 0; j < 4; j++) o[i][j] *= alpha;
        }

        __syncthreads();  // everyone done reading Ks before Ps write? (Ps separate buffer; this orders P writes vs P reads)
        // Write P transposed: Ps[j][r]
#pragma unroll
        for (int jj = 0; jj < 4; jj++)
#pragma unroll
            for (int i = 0; i < 4; i++)
                Ps[(tx * 4 + jj) * PS_STRIDE + ty * 4 + i] = s[i][jj];
        __syncthreads();

        // O += P @ V
#pragma unroll 4
        for (int j = 0; j < 64; j++) {
            float a[4], b[4];
            *(float4*)&a[0] = *(const float4*)&Ps[j * PS_STRIDE + ty * 4];
            *(float4*)&b[0] = *(const float4*)&Vs[j * VS_STRIDE + tx * 4];
#pragma unroll
            for (int i = 0; i < 4; i++)
#pragma unroll
                for (int dd = 0; dd < 4; dd++)
                    o[i][dd] = fmaf(a[i], b[dd], o[i][dd]);
        }
    }

    // Finalize: O /= l, write to [B,S,D] with heads merged
    const int h = bh & (H_ - 1);
    const int bb = bh >> 4;
#pragma unroll
    for (int i = 0; i < 4; i++) {
        const float inv = 1.0f / lrow[i];
        const int srow = q0 + ty * 4 + i;
        float4 ov = make_float4(o[i][0] * inv, o[i][1] * inv, o[i][2] * inv, o[i][3] * inv);
        *(float4*)&Oout[((size_t)bb * S_ + srow) * D_ + h * HD_ + tx * 4] = ov;
    }
}

// ---------------------------------------------------------------------------

extern "C" void kernel_launch(void* const* d_in, const int* in_sizes, int n_in,
                              void* d_out, int out_size)
{
    (void)in_sizes; (void)n_in; (void)out_size;
    const float* x  = (const float*)d_in[0];
    const float* Wq = (const float*)d_in[1];
    const float* bq = (const float*)d_in[2];
    const float* Wk = (const float*)d_in[3];
    const float* bk = (const float*)d_in[4];
    const float* Wv = (const float*)d_in[5];
    const float* bv = (const float*)d_in[6];
    const float* Wo = (const float*)d_in[7];
    const float* bo = (const float*)d_in[8];
    float* out = (float*)d_out;

    float *q, *k, *v, *att;
    cudaGetSymbolAddress((void**)&q,   g_q);
    cudaGetSymbolAddress((void**)&k,   g_k);
    cudaGetSymbolAddress((void**)&v,   g_v);
    cudaGetSymbolAddress((void**)&att, g_att);

    const size_t flash_smem = FLASH_SMEM_FLOATS * sizeof(float);  // ~68.9 KB
    cudaFuncSetAttribute(flash_kernel,
                         cudaFuncAttributeMaxDynamicSharedMemorySize,
                         (int)flash_smem);

    const int M = B_ * S_;  // 4096
    dim3 ggemm(D_ / 128, M / 128);  // (8, 32)
    dim3 tgemm(256);

    sgemm_kernel<1><<<ggemm, tgemm>>>(x, Wq, bq, q, M, D_, D_);
    sgemm_kernel<1><<<ggemm, tgemm>>>(x, Wk, bk, k, M, D_, D_);
    sgemm_kernel<1><<<ggemm, tgemm>>>(x, Wv, bv, v, M, D_, D_);

    dim3 gflash(S_ / 64, B_ * H_);  // (32, 32)
    flash_kernel<<<gflash, 256, flash_smem>>>(q, k, v, att);

    sgemm_kernel<0><<<ggemm, tgemm>>>(att, Wo, bo, out, M, D_, D_);
}

// round 2
// speedup vs baseline: 1.0532x; 1.0532x over previous
#include <cuda_runtime.h>
#include <math.h>

#define B_ 2
#define S_ 2048
#define D_ 1024
#define H_ 16
#define HD_ 64

// Scratch (allocation-free rule: __device__ globals)
__device__ float g_q[B_ * S_ * D_];
__device__ float g_k[B_ * S_ * D_];
__device__ float g_v[B_ * S_ * D_];
__device__ float g_att[B_ * S_ * D_];

// ---------------------------------------------------------------------------
// SGEMM: C[M,N] = A[M,K] @ W[K,N] + bias
// 128x128 block tile, BK=8, 256 threads, 8x8 micro-tile per thread.
// SCATTER=1 writes output in [B,H,S,HD] head layout instead of [M,N].
// ---------------------------------------------------------------------------
template <int SCATTER>
__global__ __launch_bounds__(256) void sgemm_kernel(
    const float* __restrict__ A, const float* __restrict__ W,
    const float* __restrict__ bias, float* __restrict__ C,
    int M, int N, int K)
{
    __shared__ float As[8][128];   // transposed: As[k][m]
    __shared__ float Bs[8][128];   // Bs[k][n]

    const int tid = threadIdx.x;
    const int tx = tid & 15;
    const int ty = tid >> 4;
    const int m0 = blockIdx.y * 128;
    const int n0 = blockIdx.x * 128;

    float acc[8][8];
#pragma unroll
    for (int i = 0; i < 8; i++)
#pragma unroll
        for (int j = 0; j < 8; j++) acc[i][j] = 0.0f;

    const int ar = tid >> 1;          // 0..127
    const int ac = (tid & 1) * 4;     // 0 or 4
    const int br = tid >> 5;          // 0..7
    const int bc = (tid & 31) * 4;    // 0..124

    const float* Aptr = A + (size_t)(m0 + ar) * K + ac;
    const float* Wptr = W + (size_t)br * N + n0 + bc;

    for (int kt = 0; kt < K; kt += 8) {
        float4 av = *(const float4*)(Aptr + kt);
        float4 bv = *(const float4*)(Wptr + (size_t)kt * N);
        __syncthreads();
        As[ac + 0][ar] = av.x;
        As[ac + 1][ar] = av.y;
        As[ac + 2][ar] = av.z;
        As[ac + 3][ar] = av.w;
        *(float4*)&Bs[br][bc] = bv;
        __syncthreads();

#pragma unroll
        for (int kk = 0; kk < 8; kk++) {
            float a[8], b[8];
            *(float4*)&a[0] = *(const float4*)&As[kk][ty * 8];
            *(float4*)&a[4] = *(const float4*)&As[kk][ty * 8 + 4];
            *(float4*)&b[0] = *(const float4*)&Bs[kk][tx * 8];
            *(float4*)&b[4] = *(const float4*)&Bs[kk][tx * 8 + 4];
#pragma unroll
            for (int i = 0; i < 8; i++)
#pragma unroll
                for (int j = 0; j < 8; j++)
                    acc[i][j] = fmaf(a[i], b[j], acc[i][j]);
        }
    }

#pragma unroll
    for (int i = 0; i < 8; i++) {
        const int m = m0 + ty * 8 + i;
#pragma unroll
        for (int j = 0; j < 8; j++) {
            const int n = n0 + tx * 8 + j;
            const float v = acc[i][j] + bias[n];
            if (SCATTER) {
                const int bb = m >> 11;          // m / S_
                const int s  = m & (S_ - 1);
                const int h  = n >> 6;           // n / HD_
                const int d  = n & (HD_ - 1);
                C[((size_t)(bb * H_ + h) * S_ + s) * HD_ + d] = v;
            } else {
                C[(size_t)m * N + n] = v;
            }
        }
    }
}

// ---------------------------------------------------------------------------
// Flash attention: one CTA = one (b,h) x 64-query tile. 256 threads (16x16),
// 4x4 micro-tiles for both QK^T and PV 64x64x64 GEMMs. Online softmax with
// 16-lane shfl reductions. Writes [B,S,D] (heads re-merged).
// ---------------------------------------------------------------------------
#define QS_STRIDE 68
#define KS_STRIDE 65
#define VS_STRIDE 68
#define PS_STRIDE 68
#define FLASH_SMEM_FLOATS (64 * QS_STRIDE + 64 * KS_STRIDE + 64 * VS_STRIDE + 64 * PS_STRIDE)

__global__ __launch_bounds__(256) void flash_kernel(
    const float* __restrict__ Q, const float* __restrict__ K,
    const float* __restrict__ V, float* __restrict__ Oout)
{
    extern __shared__ float sm[];
    float* Qs = sm;                     // [d][r] transposed, stride 68
    float* Ks = Qs + 64 * QS_STRIDE;    // [j][d], stride 65
    float* Vs = Ks + 64 * KS_STRIDE;    // [j][d], stride 68
    float* Ps = Vs + 64 * VS_STRIDE;    // [j][r] (P transposed), stride 68

    const int tid = threadIdx.x;
    const int tx = tid & 15;
    const int ty = tid >> 4;
    const int q0 = blockIdx.x * 64;
    const int bh = blockIdx.y;          // b*H + h

    const float* Qb = Q + (size_t)bh * S_ * HD_;
    const float* Kb = K + (size_t)bh * S_ * HD_;
    const float* Vb = V + (size_t)bh * S_ * HD_;

    const float scale = 0.125f;  // 1/sqrt(64)

    // Load Q tile (pre-scaled), store transposed Qs[d][r]
    {
        const int r0 = tid >> 4;            // 0..15
        const int d4 = (tid & 15) * 4;      // 0..60
#pragma unroll
        for (int it = 0; it < 4; it++) {
            const int r = r0 + it * 16;
            float4 qv = *(const float4*)&Qb[(size_t)(q0 + r) * HD_ + d4];
            Qs[(d4 + 0) * QS_STRIDE + r] = qv.x * scale;
            Qs[(d4 + 1) * QS_STRIDE + r] = qv.y * scale;
            Qs[(d4 + 2) * QS_STRIDE + r] = qv.z * scale;
            Qs[(d4 + 3) * QS_STRIDE + r] = qv.w * scale;
        }
    }

    float o[4][4];
    float mrow[4], lrow[4];
#pragma unroll
    for (int i = 0; i < 4; i++) {
        mrow[i] = -INFINITY;
        lrow[i] = 0.0f;
#pragma unroll
        for (int j = 0; j < 4; j++) o[i][j] = 0.0f;
    }

    for (int kt = 0; kt < S_; kt += 64) {
        __syncthreads();  // protect Qs (first iter) / Ps,Vs (later) before overwrite
        // Load K and V tiles
        {
            const int r0 = tid >> 4;
            const int d4 = (tid & 15) * 4;
#pragma unroll
            for (int it = 0; it < 4; it++) {
                const int j = r0 + it * 16;
                float4 kv = *(const float4*)&Kb[(size_t)(kt + j) * HD_ + d4];
                Ks[j * KS_STRIDE + d4 + 0] = kv.x;
                Ks[j * KS_STRIDE + d4 + 1] = kv.y;
                Ks[j * KS_STRIDE + d4 + 2] = kv.z;
                Ks[j * KS_STRIDE + d4 + 3] = kv.w;
                float4 vv = *(const float4*)&Vb[(size_t)(kt + j) * HD_ + d4];
                *(float4*)&Vs[j * VS_STRIDE + d4] = vv;
            }
        }
        __syncthreads();

        // S = Q @ K^T (Q pre-scaled)
        float s[4][4];
#pragma unroll
        for (int i = 0; i < 4; i++)
#pragma unroll
            for (int j = 0; j < 4; j++) s[i][j] = 0.0f;

#pragma unroll 4
        for (int d = 0; d < 64; d++) {
            float a[4];
            *(float4*)&a[0] = *(const float4*)&Qs[d * QS_STRIDE + ty * 4];
            float b[4];
            b[0] = Ks[(tx * 4 + 0) * KS_STRIDE + d];
            b[1] = Ks[(tx * 4 + 1) * KS_STRIDE + d];
            b[2] = Ks[(tx * 4 + 2) * KS_STRIDE + d];
            b[3] = Ks[(tx * 4 + 3) * KS_STRIDE + d];
#pragma unroll
            for (int i = 0; i < 4; i++)
#pragma unroll
                for (int j = 0; j < 4; j++)
                    s[i][j] = fmaf(a[i], b[j], s[i][j]);
        }

        // Online softmax update (row groups = 16 consecutive lanes)
#pragma unroll
        for (int i = 0; i < 4; i++) {
            float tm = fmaxf(fmaxf(s[i][0], s[i][1]), fmaxf(s[i][2], s[i][3]));
            tm = fmaxf(tm, __shfl_xor_sync(0xffffffffu, tm, 8));
            tm = fmaxf(tm, __shfl_xor_sync(0xffffffffu, tm, 4));
            tm = fmaxf(tm, __shfl_xor_sync(0xffffffffu, tm, 2));
            tm = fmaxf(tm, __shfl_xor_sync(0xffffffffu, tm, 1));
            const float mn = fmaxf(mrow[i], tm);
            const float alpha = __expf(mrow[i] - mn);
            mrow[i] = mn;
            float rs = 0.0f;
#pragma unroll
            for (int j = 0; j < 4; j++) {
                const float p = __expf(s[i][j] - mn);
                s[i][j] = p;
                rs += p;
            }
            rs += __shfl_xor_sync(0xffffffffu, rs, 8);
            rs += __shfl_xor_sync(0xffffffffu, rs, 4);
            rs += __shfl_xor_sync(0xffffffffu, rs, 2);
            rs += __shfl_xor_sync(0xffffffffu, rs, 1);
            lrow[i] = lrow[i] * alpha + rs;
#pragma unroll
            for (int j = 0; j < 4; j++) o[i][j] *= alpha;
        }

        __syncthreads();  // everyone done reading Ks before Ps write? (Ps separate buffer; this orders P writes vs P reads)
        // Write P transposed: Ps[j][r]
#pragma unroll
        for (int jj = 0; jj < 4; jj++)
#pragma unroll
            for (int i = 0; i < 4; i++)
                Ps[(tx * 4 + jj) * PS_STRIDE + ty * 4 + i] = s[i][jj];
        __syncthreads();

        // O += P @ V
#pragma unroll 4
        for (int j = 0; j < 64; j++) {
            float a[4], b[4];
            *(float4*)&a[0] = *(const float4*)&Ps[j * PS_STRIDE + ty * 4];
            *(float4*)&b[0] = *(const float4*)&Vs[j * VS_STRIDE + tx * 4];
#pragma unroll
            for (int i = 0; i < 4; i++)
#pragma unroll
                for (int dd = 0; dd < 4; dd++)
                    o[i][dd] = fmaf(a[i], b[dd], o[i][dd]);
        }
    }

    // Finalize: O /= l, write to [B,S,D] with heads merged
    const int h = bh & (H_ - 1);
    const int bb = bh >> 4;
#pragma unroll
    for (int i = 0; i < 4; i++) {
        const float inv = 1.0f / lrow[i];
        const int srow = q0 + ty * 4 + i;
        float4 ov = make_float4(o[i][0] * inv, o[i][1] * inv, o[i][2] * inv, o[i][3] * inv);
        *(float4*)&Oout[((size_t)bb * S_ + srow) * D_ + h * HD_ + tx * 4] = ov;
    }
}

// ---------------------------------------------------------------------------

extern "C" void kernel_launch(void* const* d_in, const int* in_sizes, int n_in,
                              void* d_out, int out_size)
{
    (void)in_sizes; (void)n_in; (void)out_size;
    const float* x  = (const float*)d_in[0];
    const float* Wq = (const float*)d_in[1];
    const float* bq = (const float*)d_in[2];
    const float* Wk = (const float*)d_in[3];
    const float* bk = (const float*)d_in[4];
    const float* Wv = (const float*)d_in[5];
    const float* bv = (const float*)d_in[6];
    const float* Wo = (const float*)d_in[7];
    const float* bo = (const float*)d_in[8];
    float* out = (float*)d_out;

    float *q, *k, *v, *att;
    cudaGetSymbolAddress((void**)&q,   g_q);
    cudaGetSymbolAddress((void**)&k,   g_k);
    cudaGetSymbolAddress((void**)&v,   g_v);
    cudaGetSymbolAddress((void**)&att, g_att);

    const size_t flash_smem = FLASH_SMEM_FLOATS * sizeof(float);  // ~68.9 KB
    cudaFuncSetAttribute(flash_kernel,
                         cudaFuncAttributeMaxDynamicSharedMemorySize,
                         (int)flash_smem);

    const int M = B_ * S_;  // 4096
    dim3 ggemm(D_ / 128, M / 128);  // (8, 32)
    dim3 tgemm(256);

    sgemm_kernel<1><<<ggemm, tgemm>>>(x, Wq, bq, q, M, D_, D_);
    sgemm_kernel<1><<<ggemm, tgemm>>>(x, Wk, bk, k, M, D_, D_);
    sgemm_kernel<1><<<ggemm, tgemm>>>(x, Wv, bv, v, M, D_, D_);

    dim3 gflash(S_ / 64, B_ * H_);  // (32, 32)
    flash_kernel<<<gflash, 256, flash_smem>>>(q, k, v, att);

    sgemm_kernel<0><<<ggemm, tgemm>>>(att, Wo, bo, out, M, D_, D_);
}

// round 4
// speedup vs baseline: 1.4287x; 1.3565x over previous
#include <cuda_runtime.h>
#include <cuda_bf16.h>
#include <math.h>
#include <stdint.h>

#define B_ 2
#define S_ 2048
#define D_ 1024
#define H_ 16
#define HD_ 64
#define M_ 4096

// ---------------- scratch (__device__ globals; allocation-free rule) -------
__device__ float g_q[M_ * D_];
__device__ float g_k[M_ * D_];
__device__ float g_v[M_ * D_];
__device__ float g_att[M_ * D_];
__device__ __nv_bfloat16 g_xhi[M_ * D_];
__device__ __nv_bfloat16 g_xlo[M_ * D_];
__device__ __nv_bfloat16 g_ahi[M_ * D_];
__device__ __nv_bfloat16 g_alo[M_ * D_];
__device__ __nv_bfloat16 g_wthi[4 * D_ * D_];   // W^T as [n][k], bf16 hi
__device__ __nv_bfloat16 g_wtlo[4 * D_ * D_];   // bf16 lo

// ---------------- helpers ---------------------------------------------------
__device__ __forceinline__ uint32_t smem_u32(const void* p) {
    uint32_t a;
    asm("{ .reg .u64 t; cvta.to.shared.u64 t, %1; cvt.u32.u64 %0, t; }"
        : "=r"(a) : "l"(p));
    return a;
}
__device__ __forceinline__ void cp16(uint32_t dst, const void* src) {
    asm volatile("cp.async.cg.shared.global [%0], [%1], 16;" :: "r"(dst), "l"(src));
}
__device__ __forceinline__ void cp_commit() {
    asm volatile("cp.async.commit_group;" ::: "memory");
}
__device__ __forceinline__ void cp_wait1() {
    asm volatile("cp.async.wait_group 1;" ::: "memory");
}
__device__ __forceinline__ void cp_wait0() {
    asm volatile("cp.async.wait_group 0;" ::: "memory");
}
__device__ __forceinline__ void ldsm4(uint32_t* r, uint32_t addr) {
    asm volatile("ldmatrix.sync.aligned.m8n8.x4.shared.b16 {%0,%1,%2,%3}, [%4];"
                 : "=r"(r[0]), "=r"(r[1]), "=r"(r[2]), "=r"(r[3]) : "r"(addr));
}
__device__ __forceinline__ void mma16816(float* c, const uint32_t* a,
                                         uint32_t b0, uint32_t b1) {
    asm volatile(
        "mma.sync.aligned.m16n8k16.row.col.f32.bf16.bf16.f32 "
        "{%0,%1,%2,%3}, {%4,%5,%6,%7}, {%8,%9}, {%0,%1,%2,%3};"
        : "+f"(c[0]), "+f"(c[1]), "+f"(c[2]), "+f"(c[3])
        : "r"(a[0]), "r"(a[1]), "r"(a[2]), "r"(a[3]), "r"(b0), "r"(b1));
}

// ---------------------------------------------------------------------------
// Conversion kernels
// ---------------------------------------------------------------------------
__global__ void split_kernel(const float* __restrict__ src,
                             __nv_bfloat16* __restrict__ hi,
                             __nv_bfloat16* __restrict__ lo, int n)
{
    int i = (blockIdx.x * blockDim.x + threadIdx.x) * 4;
    if (i >= n) return;
    float4 v = *(const float4*)(src + i);
    __nv_bfloat16 h0 = __float2bfloat16(v.x), h1 = __float2bfloat16(v.y);
    __nv_bfloat16 h2 = __float2bfloat16(v.z), h3 = __float2bfloat16(v.w);
    __nv_bfloat162 hp0; hp0.x = h0; hp0.y = h1;
    __nv_bfloat162 hp1; hp1.x = h2; hp1.y = h3;
    *(__nv_bfloat162*)(hi + i)     = hp0;
    *(__nv_bfloat162*)(hi + i + 2) = hp1;
    __nv_bfloat162 lp0, lp1;
    lp0.x = __float2bfloat16(v.x - __bfloat162float(h0));
    lp0.y = __float2bfloat16(v.y - __bfloat162float(h1));
    lp1.x = __float2bfloat16(v.z - __bfloat162float(h2));
    lp1.y = __float2bfloat16(v.w - __bfloat162float(h3));
    *(__nv_bfloat162*)(lo + i)     = lp0;
    *(__nv_bfloat162*)(lo + i + 2) = lp1;
}

__global__ void transW_kernel(const float* __restrict__ W0, const float* __restrict__ W1,
                              const float* __restrict__ W2, const float* __restrict__ W3,
                              __nv_bfloat16* __restrict__ ohi, __nv_bfloat16* __restrict__ olo)
{
    __shared__ float t[32][33];
    const int z = blockIdx.z;
    const float* W = (z == 0) ? W0 : (z == 1) ? W1 : (z == 2) ? W2 : W3;
    const int n0 = blockIdx.x * 32, k0 = blockIdx.y * 32;
    const int tx = threadIdx.x, ty = threadIdx.y;   // (32,8)
#pragma unroll
    for (int i = 0; i < 4; i++)
        t[ty + 8 * i][tx] = W[(size_t)(k0 + ty + 8 * i) * D_ + n0 + tx];
    __syncthreads();
    __nv_bfloat16* Oh = ohi + (size_t)z * D_ * D_;
    __nv_bfloat16* Ol = olo + (size_t)z * D_ * D_;
#pragma unroll
    for (int i = 0; i < 4; i++) {
        const int n = n0 + ty + 8 * i;
        const int k = k0 + tx;
        const float v = t[tx][ty + 8 * i];
        __nv_bfloat16 h = __float2bfloat16(v);
        Oh[(size_t)n * D_ + k] = h;
        Ol[(size_t)n * D_ + k] = __float2bfloat16(v - __bfloat162float(h));
    }
}

// ---------------------------------------------------------------------------
// mma.sync bf16 GEMM (hi/lo split, 3 terms): C = A @ Wt^T + bias
// CTA: 128x128 tile, 256 threads (8 warps, 4x2), BK=32, double-buffered.
// ---------------------------------------------------------------------------
#define BK 32
#define ROWB 80                  // bytes per smem row (40 bf16; 16B aligned, conflict-free)
#define BUF_B (128 * ROWB)       // 10240 per buffer
#define STAGE_B (4 * BUF_B)      // Ah,Al,Bh,Bl
#define GEMM_SMEM (2 * STAGE_B)  // 81920

template <int SCATTER>
__global__ __launch_bounds__(256) void gemm_mma_kernel(
    const __nv_bfloat16* __restrict__ Ah, const __nv_bfloat16* __restrict__ Al,
    const __nv_bfloat16* __restrict__ Wth, const __nv_bfloat16* __restrict__ Wtl,
    const float* __restrict__ b0p, const float* __restrict__ b1p,
    const float* __restrict__ b2p,
    float* __restrict__ o0, float* __restrict__ o1, float* __restrict__ o2)
{
    extern __shared__ __align__(16) char smem[];
    const uint32_t sbase = smem_u32(smem);
    const int tid  = threadIdx.x;
    const int wid  = tid >> 5;
    const int lane = tid & 31;
    const int wm   = wid & 3;        // 4 warps down M (32 rows each)
    const int wn   = wid >> 2;       // 2 warps across N (64 cols each)
    const int n0 = blockIdx.x * 128;
    const int m0 = blockIdx.y * 128;
    const int z  = blockIdx.z;

    const __nv_bfloat16* Bh = Wth + (size_t)z * D_ * D_;
    const __nv_bfloat16* Bl = Wtl + (size_t)z * D_ * D_;
    const float* bias = (z == 0) ? b0p : (z == 1) ? b1p : b2p;
    float* Cout = (z == 0) ? o0 : (z == 1) ? o1 : o2;

    float c[2][8][4];
#pragma unroll
    for (int i = 0; i < 2; i++)
#pragma unroll
        for (int j = 0; j < 8; j++)
#pragma unroll
            for (int q = 0; q < 4; q++) c[i][j][q] = 0.0f;

    // per-thread cp.async slice: 2 16B units x 4 buffers per stage
    const int u0 = tid * 2;

    auto load_chunk = [&](int stage, int kc) {
        const uint32_t sb = sbase + stage * STAGE_B;
#pragma unroll
        for (int u = 0; u < 2; u++) {
            const int idx = u0 + u;          // 0..511
            const int row = idx >> 2;
            const int c4  = idx & 3;
            const uint32_t off = (uint32_t)(row * ROWB + c4 * 16);
            const size_t gA = (size_t)(m0 + row) * D_ + kc * BK + c4 * 8;
            const size_t gB = (size_t)(n0 + row) * D_ + kc * BK + c4 * 8;
            cp16(sb +             off, Ah + gA);
            cp16(sb + 1 * BUF_B + off, Al + gA);
            cp16(sb + 2 * BUF_B + off, Bh + gB);
            cp16(sb + 3 * BUF_B + off, Bl + gB);
        }
        cp_commit();
    };

    // ldmatrix per-lane base offsets
    const uint32_t a_lane = (uint32_t)((wm * 32 + (lane & 15)) * ROWB + (lane >> 4) * 16);
    const uint32_t b_lane = (uint32_t)((wn * 64 + ((lane >> 4) & 1) * 8 + (lane & 7)) * ROWB
                                       + ((lane >> 3) & 1) * 16);

    const int NCHUNK = D_ / BK;   // 32
    load_chunk(0, 0);
    load_chunk(1, 1);

    for (int i = 0; i < NCHUNK; i++) {
        if (i < NCHUNK - 1) cp_wait1(); else cp_wait0();
        __syncthreads();

        const uint32_t stg = sbase + (i & 1) * STAGE_B;
        const uint32_t aBuf[3] = { stg + 0u,         stg + 0u,         stg + 1u * BUF_B };
        const uint32_t bBuf[3] = { stg + 2u * BUF_B, stg + 3u * BUF_B, stg + 2u * BUF_B };

#pragma unroll
        for (int t = 0; t < 3; t++) {
#pragma unroll
            for (int kkb = 0; kkb < 2; kkb++) {
                uint32_t a[2][4];
                ldsm4(a[0], aBuf[t] + a_lane + 0 * 16 * ROWB + kkb * 32);
                ldsm4(a[1], aBuf[t] + a_lane + 1 * 16 * ROWB + kkb * 32);
                uint32_t b[4][4];
#pragma unroll
                for (int np = 0; np < 4; np++)
                    ldsm4(b[np], bBuf[t] + b_lane + np * 16 * ROWB + kkb * 32);
#pragma unroll
                for (int mt = 0; mt < 2; mt++)
#pragma unroll
                    for (int nt = 0; nt < 8; nt++)
                        mma16816(c[mt][nt], a[mt],
                                 b[nt >> 1][(nt & 1) * 2], b[nt >> 1][(nt & 1) * 2 + 1]);
            }
        }
        __syncthreads();
        if (i + 2 < NCHUNK) load_chunk(i & 1, i + 2);
    }

    // Epilogue: bias + store (optionally head-scattered). Each warp's 64-col
    // slice is exactly one head (n-base multiple of 64).
    const int nb = n0 + wn * 64;
#pragma unroll
    for (int mt = 0; mt < 2; mt++) {
        const int r0 = m0 + wm * 32 + mt * 16 + (lane >> 2);
#pragma unroll
        for (int nt = 0; nt < 8; nt++) {
            const int d = nt * 8 + (lane & 3) * 2;
            const int ng = nb + d;
            const float bx = bias[ng], by = bias[ng + 1];
            float2 v0 = make_float2(c[mt][nt][0] + bx, c[mt][nt][1] + by);
            float2 v1 = make_float2(c[mt][nt][2] + bx, c[mt][nt][3] + by);
            if (SCATTER) {
                const int h = ng >> 6;
                const int dd = ng & 63;
                const int bb0 = r0 >> 11, sI0 = r0 & (S_ - 1);
                *(float2*)&Cout[((size_t)(bb0 * H_ + h) * S_ + sI0) * HD_ + dd] = v0;
                const int r1 = r0 + 8;
                const int bb1 = r1 >> 11, sI1 = r1 & (S_ - 1);
                *(float2*)&Cout[((size_t)(bb1 * H_ + h) * S_ + sI1) * HD_ + dd] = v1;
            } else {
                *(float2*)&Cout[(size_t)r0 * D_ + ng] = v0;
                *(float2*)&Cout[(size_t)(r0 + 8) * D_ + ng] = v1;
            }
        }
    }
}

// ---------------------------------------------------------------------------
// Flash attention (unchanged: correct, ~1030us)
// ---------------------------------------------------------------------------
#define QS_STRIDE 68
#define KS_STRIDE 65
#define VS_STRIDE 68
#define PS_STRIDE 68
#define FLASH_SMEM_FLOATS (64 * QS_STRIDE + 64 * KS_STRIDE + 64 * VS_STRIDE + 64 * PS_STRIDE)

__global__ __launch_bounds__(256) void flash_kernel(
    const float* __restrict__ Q, const float* __restrict__ K,
    const float* __restrict__ V, float* __restrict__ Oout)
{
    extern __shared__ float sm[];
    float* Qs = sm;
    float* Ks = Qs + 64 * QS_STRIDE;
    float* Vs = Ks + 64 * KS_STRIDE;
    float* Ps = Vs + 64 * VS_STRIDE;

    const int tid = threadIdx.x;
    const int tx = tid & 15;
    const int ty = tid >> 4;
    const int q0 = blockIdx.x * 64;
    const int bh = blockIdx.y;

    const float* Qb = Q + (size_t)bh * S_ * HD_;
    const float* Kb = K + (size_t)bh * S_ * HD_;
    const float* Vb = V + (size_t)bh * S_ * HD_;
    const float scale = 0.125f;

    {
        const int r0 = tid >> 4;
        const int d4 = (tid & 15) * 4;
#pragma unroll
        for (int it = 0; it < 4; it++) {
            const int r = r0 + it * 16;
            float4 qv = *(const float4*)&Qb[(size_t)(q0 + r) * HD_ + d4];
            Qs[(d4 + 0) * QS_STRIDE + r] = qv.x * scale;
            Qs[(d4 + 1) * QS_STRIDE + r] = qv.y * scale;
            Qs[(d4 + 2) * QS_STRIDE + r] = qv.z * scale;
            Qs[(d4 + 3) * QS_STRIDE + r] = qv.w * scale;
        }
    }

    float o[4][4], mrow[4], lrow[4];
#pragma unroll
    for (int i = 0; i < 4; i++) {
        mrow[i] = -INFINITY; lrow[i] = 0.0f;
#pragma unroll
        for (int j = 0; j < 4; j++) o[i][j] = 0.0f;
    }

    for (int kt = 0; kt < S_; kt += 64) {
        __syncthreads();
        {
            const int r0 = tid >> 4;
            const int d4 = (tid & 15) * 4;
#pragma unroll
            for (int it = 0; it < 4; it++) {
                const int j = r0 + it * 16;
                float4 kv = *(const float4*)&Kb[(size_t)(kt + j) * HD_ + d4];
                Ks[j * KS_STRIDE + d4 + 0] = kv.x;
                Ks[j * KS_STRIDE + d4 + 1] = kv.y;
                Ks[j * KS_STRIDE + d4 + 2] = kv.z;
                Ks[j * KS_STRIDE + d4 + 3] = kv.w;
                float4 vv = *(const float4*)&Vb[(size_t)(kt + j) * HD_ + d4];
                *(float4*)&Vs[j * VS_STRIDE + d4] = vv;
            }
        }
        __syncthreads();

        float s[4][4];
#pragma unroll
        for (int i = 0; i < 4; i++)
#pragma unroll
            for (int j = 0; j < 4; j++) s[i][j] = 0.0f;

#pragma unroll 4
        for (int d = 0; d < 64; d++) {
            float a[4];
            *(float4*)&a[0] = *(const float4*)&Qs[d * QS_STRIDE + ty * 4];
            float b[4];
            b[0] = Ks[(tx * 4 + 0) * KS_STRIDE + d];
            b[1] = Ks[(tx * 4 + 1) * KS_STRIDE + d];
            b[2] = Ks[(tx * 4 + 2) * KS_STRIDE + d];
            b[3] = Ks[(tx * 4 + 3) * KS_STRIDE + d];
#pragma unroll
            for (int i = 0; i < 4; i++)
#pragma unroll
                for (int j = 0; j < 4; j++)
                    s[i][j] = fmaf(a[i], b[j], s[i][j]);
        }

#pragma unroll
        for (int i = 0; i < 4; i++) {
            float tm = fmaxf(fmaxf(s[i][0], s[i][1]), fmaxf(s[i][2], s[i][3]));
            tm = fmaxf(tm, __shfl_xor_sync(0xffffffffu, tm, 8));
            tm = fmaxf(tm, __shfl_xor_sync(0xffffffffu, tm, 4));
            tm = fmaxf(tm, __shfl_xor_sync(0xffffffffu, tm, 2));
            tm = fmaxf(tm, __shfl_xor_sync(0xffffffffu, tm, 1));
            const float mn = fmaxf(mrow[i], tm);
            const float alpha = __expf(mrow[i] - mn);
            mrow[i] = mn;
            float rs = 0.0f;
#pragma unroll
            for (int j = 0; j < 4; j++) {
                const float p = __expf(s[i][j] - mn);
                s[i][j] = p;
                rs += p;
            }
            rs += __shfl_xor_sync(0xffffffffu, rs, 8);
            rs += __shfl_xor_sync(0xffffffffu, rs, 4);
            rs += __shfl_xor_sync(0xffffffffu, rs, 2);
            rs += __shfl_xor_sync(0xffffffffu, rs, 1);
            lrow[i] = lrow[i] * alpha + rs;
#pragma unroll
            for (int j = 0; j < 4; j++) o[i][j] *= alpha;
        }

        __syncthreads();
#pragma unroll
        for (int jj = 0; jj < 4; jj++)
#pragma unroll
            for (int i = 0; i < 4; i++)
                Ps[(tx * 4 + jj) * PS_STRIDE + ty * 4 + i] = s[i][jj];
        __syncthreads();

#pragma unroll 4
        for (int j = 0; j < 64; j++) {
            float a[4], b[4];
            *(float4*)&a[0] = *(const float4*)&Ps[j * PS_STRIDE + ty * 4];
            *(float4*)&b[0] = *(const float4*)&Vs[j * VS_STRIDE + tx * 4];
#pragma unroll
            for (int i = 0; i < 4; i++)
#pragma unroll
                for (int dd = 0; dd < 4; dd++)
                    o[i][dd] = fmaf(a[i], b[dd], o[i][dd]);
        }
    }

    const int h = bh & (H_ - 1);
    const int bb = bh >> 4;
#pragma unroll
    for (int i = 0; i < 4; i++) {
        const float inv = 1.0f / lrow[i];
        const int srow = q0 + ty * 4 + i;
        float4 ov = make_float4(o[i][0] * inv, o[i][1] * inv, o[i][2] * inv, o[i][3] * inv);
        *(float4*)&Oout[((size_t)bb * S_ + srow) * D_ + h * HD_ + tx * 4] = ov;
    }
}

// ---------------------------------------------------------------------------

extern "C" void kernel_launch(void* const* d_in, const int* in_sizes, int n_in,
                              void* d_out, int out_size)
{
    (void)in_sizes; (void)n_in; (void)out_size;
    const float* x  = (const float*)d_in[0];
    const float* Wq = (const float*)d_in[1];
    const float* bq = (const float*)d_in[2];
    const float* Wk = (const float*)d_in[3];
    const float* bk = (const float*)d_in[4];
    const float* Wv = (const float*)d_in[5];
    const float* bv = (const float*)d_in[6];
    const float* Wo = (const float*)d_in[7];
    const float* bo = (const float*)d_in[8];
    float* out = (float*)d_out;

    float *q, *k, *v, *att;
    __nv_bfloat16 *xhi, *xlo, *ahi, *alo, *wthi, *wtlo;
    cudaGetSymbolAddress((void**)&q,    g_q);
    cudaGetSymbolAddress((void**)&k,    g_k);
    cudaGetSymbolAddress((void**)&v,    g_v);
    cudaGetSymbolAddress((void**)&att,  g_att);
    cudaGetSymbolAddress((void**)&xhi,  g_xhi);
    cudaGetSymbolAddress((void**)&xlo,  g_xlo);
    cudaGetSymbolAddress((void**)&ahi,  g_ahi);
    cudaGetSymbolAddress((void**)&alo,  g_alo);
    cudaGetSymbolAddress((void**)&wthi, g_wthi);
    cudaGetSymbolAddress((void**)&wtlo, g_wtlo);

    cudaFuncSetAttribute(gemm_mma_kernel<1>,
        cudaFuncAttributeMaxDynamicSharedMemorySize, GEMM_SMEM);
    cudaFuncSetAttribute(gemm_mma_kernel<0>,
        cudaFuncAttributeMaxDynamicSharedMemorySize, GEMM_SMEM);
    cudaFuncSetAttribute(flash_kernel,
        cudaFuncAttributeMaxDynamicSharedMemorySize,
        (int)(FLASH_SMEM_FLOATS * sizeof(float)));

    const int NEL = M_ * D_;
    split_kernel<<<NEL / 4 / 256, 256>>>(x, xhi, xlo, NEL);
    transW_kernel<<<dim3(32, 32, 4), dim3(32, 8)>>>(Wq, Wk, Wv, Wo, wthi, wtlo);

    gemm_mma_kernel<1><<<dim3(8, 32, 3), 256, GEMM_SMEM>>>(
        xhi, xlo, wthi, wtlo, bq, bk, bv, q, k, v);

    flash_kernel<<<dim3(S_ / 64, B_ * H_), 256, FLASH_SMEM_FLOATS * sizeof(float)>>>(
        q, k, v, att);

    split_kernel<<<NEL / 4 / 256, 256>>>(att, ahi, alo, NEL);
    gemm_mma_kernel<0><<<dim3(8, 32, 1), 256, GEMM_SMEM>>>(
        ahi, alo, wthi + (size_t)3 * D_ * D_, wtlo + (size_t)3 * D_ * D_,
        bo, bo, bo, out, out, out);
}

// round 6
// speedup vs baseline: 2.8453x; 1.9916x over previous
#include <cuda_runtime.h>
#include <cuda_bf16.h>
#include <math.h>
#include <stdint.h>

#define B_ 2
#define S_ 2048
#define D_ 1024
#define H_ 16
#define HD_ 64
#define M_ 4096

// ---------------- scratch (__device__ globals; allocation-free rule) -------
__device__ __nv_bfloat16 g_xhi[M_ * D_];
__device__ __nv_bfloat16 g_xlo[M_ * D_];
__device__ __nv_bfloat16 g_ahi[M_ * D_];
__device__ __nv_bfloat16 g_alo[M_ * D_];
__device__ __nv_bfloat16 g_wthi[4 * D_ * D_];   // W^T as [n][k], bf16 hi
__device__ __nv_bfloat16 g_wtlo[4 * D_ * D_];   // bf16 lo
__device__ __nv_bfloat16 g_qh[M_ * D_];         // [B,H,S,HD] layouts
__device__ __nv_bfloat16 g_ql[M_ * D_];
__device__ __nv_bfloat16 g_kh[M_ * D_];
__device__ __nv_bfloat16 g_kl[M_ * D_];
__device__ __nv_bfloat16 g_vh[M_ * D_];
__device__ __nv_bfloat16 g_vl[M_ * D_];

// ---------------- helpers ---------------------------------------------------
__device__ __forceinline__ uint32_t smem_u32(const void* p) {
    uint32_t a;
    asm("{ .reg .u64 t; cvta.to.shared.u64 t, %1; cvt.u32.u64 %0, t; }"
        : "=r"(a) : "l"(p));
    return a;
}
__device__ __forceinline__ void cp16(uint32_t dst, const void* src) {
    asm volatile("cp.async.cg.shared.global [%0], [%1], 16;" :: "r"(dst), "l"(src));
}
__device__ __forceinline__ void cp_commit() {
    asm volatile("cp.async.commit_group;" ::: "memory");
}
__device__ __forceinline__ void cp_wait1() {
    asm volatile("cp.async.wait_group 1;" ::: "memory");
}
__device__ __forceinline__ void cp_wait0() {
    asm volatile("cp.async.wait_group 0;" ::: "memory");
}
__device__ __forceinline__ void ldsm4(uint32_t* r, uint32_t addr) {
    asm volatile("ldmatrix.sync.aligned.m8n8.x4.shared.b16 {%0,%1,%2,%3}, [%4];"
                 : "=r"(r[0]), "=r"(r[1]), "=r"(r[2]), "=r"(r[3]) : "r"(addr));
}
__device__ __forceinline__ void ldsm4t(uint32_t* r, uint32_t addr) {
    asm volatile("ldmatrix.sync.aligned.m8n8.x4.trans.shared.b16 {%0,%1,%2,%3}, [%4];"
                 : "=r"(r[0]), "=r"(r[1]), "=r"(r[2]), "=r"(r[3]) : "r"(addr));
}
__device__ __forceinline__ void mma16816(float* c, const uint32_t* a,
                                         uint32_t b0, uint32_t b1) {
    asm volatile(
        "mma.sync.aligned.m16n8k16.row.col.f32.bf16.bf16.f32 "
        "{%0,%1,%2,%3}, {%4,%5,%6,%7}, {%8,%9}, {%0,%1,%2,%3};"
        : "+f"(c[0]), "+f"(c[1]), "+f"(c[2]), "+f"(c[3])
        : "r"(a[0]), "r"(a[1]), "r"(a[2]), "r"(a[3]), "r"(b0), "r"(b1));
}
// XOR swizzle: 128B rows of 8 x 16B units
#define SWF(r, c) ((uint32_t)((r) * 128 + ((((c) ^ ((r) & 7))) << 4)))

__device__ __forceinline__ uint32_t pack_bf16_hi(float x, float y,
                                                 float& rx, float& ry) {
    __nv_bfloat16 hx = __float2bfloat16_rn(x);
    __nv_bfloat16 hy = __float2bfloat16_rn(y);
    rx = x - __bfloat162float(hx);
    ry = y - __bfloat162float(hy);
    __nv_bfloat162 p; p.x = hx; p.y = hy;
    return *(uint32_t*)&p;
}
__device__ __forceinline__ uint32_t pack_bf16(float x, float y) {
    __nv_bfloat162 p;
    p.x = __float2bfloat16_rn(x);
    p.y = __float2bfloat16_rn(y);
    return *(uint32_t*)&p;
}

// ---------------------------------------------------------------------------
// Conversion kernels
// ---------------------------------------------------------------------------
__global__ void split_kernel(const float* __restrict__ src,
                             __nv_bfloat16* __restrict__ hi,
                             __nv_bfloat16* __restrict__ lo, int n)
{
    int i = (blockIdx.x * blockDim.x + threadIdx.x) * 4;
    if (i >= n) return;
    float4 v = *(const float4*)(src + i);
    float lx, ly, lz, lw;
    uint32_t h0 = pack_bf16_hi(v.x, v.y, lx, ly);
    uint32_t h1 = pack_bf16_hi(v.z, v.w, lz, lw);
    *(uint32_t*)(hi + i)     = h0;
    *(uint32_t*)(hi + i + 2) = h1;
    *(uint32_t*)(lo + i)     = pack_bf16(lx, ly);
    *(uint32_t*)(lo + i + 2) = pack_bf16(lz, lw);
}

__global__ void transW_kernel(const float* __restrict__ W0, const float* __restrict__ W1,
                              const float* __restrict__ W2, const float* __restrict__ W3,
                              __nv_bfloat16* __restrict__ ohi, __nv_bfloat16* __restrict__ olo)
{
    __shared__ float t[32][33];
    const int z = blockIdx.z;
    const float* W = (z == 0) ? W0 : (z == 1) ? W1 : (z == 2) ? W2 : W3;
    const int n0 = blockIdx.x * 32, k0 = blockIdx.y * 32;
    const int tx = threadIdx.x, ty = threadIdx.y;   // (32,8)
#pragma unroll
    for (int i = 0; i < 4; i++)
        t[ty + 8 * i][tx] = W[(size_t)(k0 + ty + 8 * i) * D_ + n0 + tx];
    __syncthreads();
    __nv_bfloat16* Oh = ohi + (size_t)z * D_ * D_;
    __nv_bfloat16* Ol = olo + (size_t)z * D_ * D_;
#pragma unroll
    for (int i = 0; i < 4; i++) {
        const int n = n0 + ty + 8 * i;
        const int k = k0 + tx;
        const float v = t[tx][ty + 8 * i];
        __nv_bfloat16 h = __float2bfloat16_rn(v);
        Oh[(size_t)n * D_ + k] = h;
        Ol[(size_t)n * D_ + k] = __float2bfloat16_rn(v - __bfloat162float(h));
    }
}

// ---------------------------------------------------------------------------
// mma.sync bf16 GEMM (hi/lo split, 3 terms): C = A @ Wt^T + bias
// CTA 128x128, 256 threads (8 warps 4x2), BK=32, double buffered.
// SCATTER=1: write bf16 hi/lo pairs scattered to [B,H,S,HD] (z-selected),
//            with Q (z==0) pre-scaled by 0.125.
// SCATTER=0: write fp32 row-major [M,D].
// ---------------------------------------------------------------------------
#define BK 32
#define ROWB 80
#define BUF_B (128 * ROWB)
#define STAGE_B (4 * BUF_B)
#define GEMM_SMEM (2 * STAGE_B)

template <int SCATTER>
__global__ __launch_bounds__(256) void gemm_mma_kernel(
    const __nv_bfloat16* __restrict__ Ah, const __nv_bfloat16* __restrict__ Al,
    const __nv_bfloat16* __restrict__ Wth, const __nv_bfloat16* __restrict__ Wtl,
    const float* __restrict__ b0p, const float* __restrict__ b1p,
    const float* __restrict__ b2p,
    float* __restrict__ fo,
    __nv_bfloat16* __restrict__ oh0, __nv_bfloat16* __restrict__ ol0,
    __nv_bfloat16* __restrict__ oh1, __nv_bfloat16* __restrict__ ol1,
    __nv_bfloat16* __restrict__ oh2, __nv_bfloat16* __restrict__ ol2)
{
    extern __shared__ __align__(16) char smem[];
    const uint32_t sbase = smem_u32(smem);
    const int tid  = threadIdx.x;
    const int wid  = tid >> 5;
    const int lane = tid & 31;
    const int wm   = wid & 3;
    const int wn   = wid >> 2;
    const int n0 = blockIdx.x * 128;
    const int m0 = blockIdx.y * 128;
    const int z  = blockIdx.z;

    const __nv_bfloat16* Bh = Wth + (size_t)z * D_ * D_;
    const __nv_bfloat16* Bl = Wtl + (size_t)z * D_ * D_;
    const float* bias = (z == 0) ? b0p : (z == 1) ? b1p : b2p;
    __nv_bfloat16* Ohp = (z == 0) ? oh0 : (z == 1) ? oh1 : oh2;
    __nv_bfloat16* Olp = (z == 0) ? ol0 : (z == 1) ? ol1 : ol2;
    const float scl = (SCATTER && z == 0) ? 0.125f : 1.0f;

    float c[2][8][4];
#pragma unroll
    for (int i = 0; i < 2; i++)
#pragma unroll
        for (int j = 0; j < 8; j++)
#pragma unroll
            for (int q = 0; q < 4; q++) c[i][j][q] = 0.0f;

    const int u0 = tid * 2;
    auto load_chunk = [&](int stage, int kc) {
        const uint32_t sb = sbase + stage * STAGE_B;
#pragma unroll
        for (int u = 0; u < 2; u++) {
            const int idx = u0 + u;
            const int row = idx >> 2;
            const int c4  = idx & 3;
            const uint32_t off = (uint32_t)(row * ROWB + c4 * 16);
            const size_t gA = (size_t)(m0 + row) * D_ + kc * BK + c4 * 8;
            const size_t gB = (size_t)(n0 + row) * D_ + kc * BK + c4 * 8;
            cp16(sb +             off, Ah + gA);
            cp16(sb + 1 * BUF_B + off, Al + gA);
            cp16(sb + 2 * BUF_B + off, Bh + gB);
            cp16(sb + 3 * BUF_B + off, Bl + gB);
        }
        cp_commit();
    };

    const uint32_t a_lane = (uint32_t)((wm * 32 + (lane & 15)) * ROWB + (lane >> 4) * 16);
    const uint32_t b_lane = (uint32_t)((wn * 64 + ((lane >> 4) & 1) * 8 + (lane & 7)) * ROWB
                                       + ((lane >> 3) & 1) * 16);

    const int NCHUNK = D_ / BK;
    load_chunk(0, 0);
    load_chunk(1, 1);

    for (int i = 0; i < NCHUNK; i++) {
        if (i < NCHUNK - 1) cp_wait1(); else cp_wait0();
        __syncthreads();

        const uint32_t stg = sbase + (i & 1) * STAGE_B;
        const uint32_t aBuf[3] = { stg + 0u,         stg + 0u,         stg + 1u * BUF_B };
        const uint32_t bBuf[3] = { stg + 2u * BUF_B, stg + 3u * BUF_B, stg + 2u * BUF_B };

#pragma unroll
        for (int t = 0; t < 3; t++) {
#pragma unroll
            for (int kkb = 0; kkb < 2; kkb++) {
                uint32_t a[2][4];
                ldsm4(a[0], aBuf[t] + a_lane + 0 * 16 * ROWB + kkb * 32);
                ldsm4(a[1], aBuf[t] + a_lane + 1 * 16 * ROWB + kkb * 32);
                uint32_t b[4][4];
#pragma unroll
                for (int np = 0; np < 4; np++)
                    ldsm4(b[np], bBuf[t] + b_lane + np * 16 * ROWB + kkb * 32);
#pragma unroll
                for (int mt = 0; mt < 2; mt++)
#pragma unroll
                    for (int nt = 0; nt < 8; nt++)
                        mma16816(c[mt][nt], a[mt],
                                 b[nt >> 1][(nt & 1) * 2], b[nt >> 1][(nt & 1) * 2 + 1]);
            }
        }
        __syncthreads();
        if (i + 2 < NCHUNK) load_chunk(i & 1, i + 2);
    }

    const int nb = n0 + wn * 64;
#pragma unroll
    for (int mt = 0; mt < 2; mt++) {
        const int r0 = m0 + wm * 32 + mt * 16 + (lane >> 2);
#pragma unroll
        for (int nt = 0; nt < 8; nt++) {
            const int ng = nb + nt * 8 + (lane & 3) * 2;
            const float bx = bias[ng], by = bias[ng + 1];
            float v0x = (c[mt][nt][0] + bx) * scl, v0y = (c[mt][nt][1] + by) * scl;
            float v1x = (c[mt][nt][2] + bx) * scl, v1y = (c[mt][nt][3] + by) * scl;
            if (SCATTER) {
                const int h = ng >> 6;
                const int dd = ng & 63;
                const int bb0 = r0 >> 11, sI0 = r0 & (S_ - 1);
                const int r1 = r0 + 8;
                const int bb1 = r1 >> 11, sI1 = r1 & (S_ - 1);
                const size_t o0i = ((size_t)(bb0 * H_ + h) * S_ + sI0) * HD_ + dd;
                const size_t o1i = ((size_t)(bb1 * H_ + h) * S_ + sI1) * HD_ + dd;
                float l0x, l0y, l1x, l1y;
                *(uint32_t*)&Ohp[o0i] = pack_bf16_hi(v0x, v0y, l0x, l0y);
                *(uint32_t*)&Olp[o0i] = pack_bf16(l0x, l0y);
                *(uint32_t*)&Ohp[o1i] = pack_bf16_hi(v1x, v1y, l1x, l1y);
                *(uint32_t*)&Olp[o1i] = pack_bf16(l1x, l1y);
            } else {
                *(float2*)&fo[(size_t)r0 * D_ + ng] = make_float2(v0x, v0y);
                *(float2*)&fo[(size_t)(r0 + 8) * D_ + ng] = make_float2(v1x, v1y);
            }
        }
    }
}

// ---------------------------------------------------------------------------
// Tensor-core flash attention.
// CTA: 128 queries x one (b,h). 8 warps, each owns 16 query rows.
// Key blocks of 64, double-buffered cp.async. 3-term bf16 hi/lo mma for
// both QK^T and PV. Online softmax in fragment registers.
// Writes attended output as bf16 hi/lo at [B,S,D] (heads merged).
// ---------------------------------------------------------------------------
#define FL_QBUF 16384                 // 128 rows x 128B
#define FL_KVST 32768                 // 4 bufs x (64 x 128B)
#define FL_SMEM (2 * FL_QBUF + 2 * FL_KVST)   // 96KB

__global__ __launch_bounds__(256) void flash_tc_kernel(
    const __nv_bfloat16* __restrict__ Qh, const __nv_bfloat16* __restrict__ Ql,
    const __nv_bfloat16* __restrict__ Kh, const __nv_bfloat16* __restrict__ Kl,
    const __nv_bfloat16* __restrict__ Vh, const __nv_bfloat16* __restrict__ Vl,
    __nv_bfloat16* __restrict__ Oh, __nv_bfloat16* __restrict__ Ol)
{
    extern __shared__ __align__(16) char smem[];
    const uint32_t base = smem_u32(smem);
    const int tid = threadIdx.x, wid = tid >> 5, lane = tid & 31;
    const int q0 = blockIdx.x * 128;
    const int bh = blockIdx.y;
    const size_t hb = (size_t)bh * S_ * HD_;

    // ---- Q tile load (hi+lo) ----
#pragma unroll
    for (int u = 0; u < 8; u++) {
        const int idx = tid + u * 256;
        const int bsel = idx >> 10;
        const int r = (idx >> 3) & 127;
        const int c = idx & 7;
        const __nv_bfloat16* src = (bsel ? Ql : Qh) + hb + (size_t)(q0 + r) * HD_ + c * 8;
        cp16(base + bsel * FL_QBUF + SWF(r, c), src);
    }
    cp_commit();

    auto loadkv = [&](int st, int kb) {
        const uint32_t sb = base + 2 * FL_QBUF + st * FL_KVST;
#pragma unroll
        for (int u = 0; u < 8; u++) {
            const int idx = tid + u * 256;
            const int b4 = idx >> 9;
            const int r = (idx >> 3) & 63;
            const int c = idx & 7;
            const __nv_bfloat16* g =
                (b4 == 0) ? Kh : (b4 == 1) ? Kl : (b4 == 2) ? Vh : Vl;
            cp16(sb + b4 * 8192 + SWF(r, c), g + hb + (size_t)(kb * 64 + r) * HD_ + c * 8);
        }
        cp_commit();
    };
    loadkv(0, 0);
    loadkv(1, 1);

    float o[8][4];
#pragma unroll
    for (int nt = 0; nt < 8; nt++)
#pragma unroll
        for (int q = 0; q < 4; q++) o[nt][q] = 0.0f;
    float m0r = -INFINITY, m1r = -INFINITY, l0 = 0.0f, l1 = 0.0f;

    // fragment lane geometry
    const int a_row = wid * 16 + (lane & 7) + ((lane >> 3) & 1) * 8;
    const int a_c   = lane >> 4;
    const int k_row = ((lane >> 4) & 1) * 8 + (lane & 7);
    const int k_c   = (lane >> 3) & 1;
    const int v_row = ((lane >> 3) & 1) * 8 + (lane & 7);
    const int v_c   = lane >> 4;

    const int NB = S_ / 64;   // 32
    for (int kb = 0; kb < NB; kb++) {
        if (kb < NB - 1) cp_wait1(); else cp_wait0();
        __syncthreads();
        const uint32_t stg = base + 2 * FL_QBUF + (kb & 1) * FL_KVST;

        // ---- S = Q K^T (3 hi/lo terms) ----
        float s[8][4];
#pragma unroll
        for (int nt = 0; nt < 8; nt++)
#pragma unroll
            for (int q = 0; q < 4; q++) s[nt][q] = 0.0f;

#pragma unroll
        for (int ks = 0; ks < 4; ks++) {
            uint32_t ah[4], al[4];
            ldsm4(ah, base +           SWF(a_row, 2 * ks + a_c));
            ldsm4(al, base + FL_QBUF + SWF(a_row, 2 * ks + a_c));
#pragma unroll
            for (int np = 0; np < 4; np++) {
                uint32_t bh4[4], bl4[4];
                ldsm4(bh4, stg +        SWF(np * 16 + k_row, 2 * ks + k_c));
                ldsm4(bl4, stg + 8192 + SWF(np * 16 + k_row, 2 * ks + k_c));
#pragma unroll
                for (int hh = 0; hh < 2; hh++) {
                    float* sc = s[2 * np + hh];
                    mma16816(sc, ah, bh4[2 * hh], bh4[2 * hh + 1]);
                    mma16816(sc, ah, bl4[2 * hh], bl4[2 * hh + 1]);
                    mma16816(sc, al, bh4[2 * hh], bh4[2 * hh + 1]);
                }
            }
        }

        // ---- online softmax (rows r = lane>>2 and r+8) ----
        float mx0 = -INFINITY, mx1 = -INFINITY;
#pragma unroll
        for (int nt = 0; nt < 8; nt++) {
            mx0 = fmaxf(mx0, fmaxf(s[nt][0], s[nt][1]));
            mx1 = fmaxf(mx1, fmaxf(s[nt][2], s[nt][3]));
        }
        mx0 = fmaxf(mx0, __shfl_xor_sync(0xffffffffu, mx0, 1));
        mx0 = fmaxf(mx0, __shfl_xor_sync(0xffffffffu, mx0, 2));
        mx1 = fmaxf(mx1, __shfl_xor_sync(0xffffffffu, mx1, 1));
        mx1 = fmaxf(mx1, __shfl_xor_sync(0xffffffffu, mx1, 2));
        const float mn0 = fmaxf(m0r, mx0);
        const float mn1 = fmaxf(m1r, mx1);
        const float al0 = __expf(m0r - mn0);
        const float al1 = __expf(m1r - mn1);
        m0r = mn0; m1r = mn1;

        float sum0 = 0.0f, sum1 = 0.0f;
#pragma unroll
        for (int nt = 0; nt < 8; nt++) {
            s[nt][0] = __expf(s[nt][0] - mn0);
            s[nt][1] = __expf(s[nt][1] - mn0);
            s[nt][2] = __expf(s[nt][2] - mn1);
            s[nt][3] = __expf(s[nt][3] - mn1);
            sum0 += s[nt][0] + s[nt][1];
            sum1 += s[nt][2] + s[nt][3];
        }
        sum0 += __shfl_xor_sync(0xffffffffu, sum0, 1);
        sum0 += __shfl_xor_sync(0xffffffffu, sum0, 2);
        sum1 += __shfl_xor_sync(0xffffffffu, sum1, 1);
        sum1 += __shfl_xor_sync(0xffffffffu, sum1, 2);
        l0 = l0 * al0 + sum0;
        l1 = l1 * al1 + sum1;
#pragma unroll
        for (int nt = 0; nt < 8; nt++) {
            o[nt][0] *= al0; o[nt][1] *= al0;
            o[nt][2] *= al1; o[nt][3] *= al1;
        }

        // ---- pack P fragments (hi/lo) ----
        uint32_t aph[4][4], apl[4][4];
#pragma unroll
        for (int kc = 0; kc < 4; kc++) {
            float lx, ly;
            aph[kc][0] = pack_bf16_hi(s[2 * kc][0], s[2 * kc][1], lx, ly);
            apl[kc][0] = pack_bf16(lx, ly);
            aph[kc][1] = pack_bf16_hi(s[2 * kc][2], s[2 * kc][3], lx, ly);
            apl[kc][1] = pack_bf16(lx, ly);
            aph[kc][2] = pack_bf16_hi(s[2 * kc + 1][0], s[2 * kc + 1][1], lx, ly);
            apl[kc][2] = pack_bf16(lx, ly);
            aph[kc][3] = pack_bf16_hi(s[2 * kc + 1][2], s[2 * kc + 1][3], lx, ly);
            apl[kc][3] = pack_bf16(lx, ly);
        }

        // ---- O += P V (3 hi/lo terms); V via ldmatrix.trans ----
        const uint32_t vhb = stg + 16384, vlb = stg + 24576;
#pragma unroll
        for (int dp = 0; dp < 4; dp++) {
#pragma unroll
            for (int kc = 0; kc < 4; kc++) {
                uint32_t vh4[4], vl4[4];
                ldsm4t(vh4, vhb + SWF(kc * 16 + v_row, 2 * dp + v_c));
                ldsm4t(vl4, vlb + SWF(kc * 16 + v_row, 2 * dp + v_c));
                mma16816(o[2 * dp],     aph[kc], vh4[0], vh4[1]);
                mma16816(o[2 * dp],     aph[kc], vl4[0], vl4[1]);
                mma16816(o[2 * dp],     apl[kc], vh4[0], vh4[1]);
                mma16816(o[2 * dp + 1], aph[kc], vh4[2], vh4[3]);
                mma16816(o[2 * dp + 1], aph[kc], vl4[2], vl4[3]);
                mma16816(o[2 * dp + 1], apl[kc], vh4[2], vh4[3]);
            }
        }
        __syncthreads();
        if (kb + 2 < NB) loadkv(kb & 1, kb + 2);
    }

    // ---- epilogue: /l, write bf16 hi/lo at [B,S,D] ----
    const float inv0 = 1.0f / l0, inv1 = 1.0f / l1;
    const int h = bh & (H_ - 1);
    const int bb = bh >> 4;
    const int r0 = q0 + wid * 16 + (lane >> 2);
    const int r1 = r0 + 8;
#pragma unroll
    for (int nt = 0; nt < 8; nt++) {
        const int gd = h * 64 + nt * 8 + (lane & 3) * 2;
        const size_t i0 = ((size_t)bb * S_ + r0) * D_ + gd;
        const size_t i1 = ((size_t)bb * S_ + r1) * D_ + gd;
        float lx, ly;
        *(uint32_t*)&Oh[i0] = pack_bf16_hi(o[nt][0] * inv0, o[nt][1] * inv0, lx, ly);
        *(uint32_t*)&Ol[i0] = pack_bf16(lx, ly);
        *(uint32_t*)&Oh[i1] = pack_bf16_hi(o[nt][2] * inv1, o[nt][3] * inv1, lx, ly);
        *(uint32_t*)&Ol[i1] = pack_bf16(lx, ly);
    }
}

// ---------------------------------------------------------------------------

extern "C" void kernel_launch(void* const* d_in, const int* in_sizes, int n_in,
                              void* d_out, int out_size)
{
    (void)in_sizes; (void)n_in; (void)out_size;
    const float* x  = (const float*)d_in[0];
    const float* Wq = (const float*)d_in[1];
    const float* bq = (const float*)d_in[2];
    const float* Wk = (const float*)d_in[3];
    const float* bk = (const float*)d_in[4];
    const float* Wv = (const float*)d_in[5];
    const float* bv = (const float*)d_in[6];
    const float* Wo = (const float*)d_in[7];
    const float* bo = (const float*)d_in[8];
    float* out = (float*)d_out;

    __nv_bfloat16 *xhi, *xlo, *ahi, *alo, *wthi, *wtlo;
    __nv_bfloat16 *qh, *ql, *kh, *kl, *vh, *vl;
    cudaGetSymbolAddress((void**)&xhi,  g_xhi);
    cudaGetSymbolAddress((void**)&xlo,  g_xlo);
    cudaGetSymbolAddress((void**)&ahi,  g_ahi);
    cudaGetSymbolAddress((void**)&alo,  g_alo);
    cudaGetSymbolAddress((void**)&wthi, g_wthi);
    cudaGetSymbolAddress((void**)&wtlo, g_wtlo);
    cudaGetSymbolAddress((void**)&qh,   g_qh);
    cudaGetSymbolAddress((void**)&ql,   g_ql);
    cudaGetSymbolAddress((void**)&kh,   g_kh);
    cudaGetSymbolAddress((void**)&kl,   g_kl);
    cudaGetSymbolAddress((void**)&vh,   g_vh);
    cudaGetSymbolAddress((void**)&vl,   g_vl);

    cudaFuncSetAttribute(gemm_mma_kernel<1>,
        cudaFuncAttributeMaxDynamicSharedMemorySize, GEMM_SMEM);
    cudaFuncSetAttribute(gemm_mma_kernel<0>,
        cudaFuncAttributeMaxDynamicSharedMemorySize, GEMM_SMEM);
    cudaFuncSetAttribute(flash_tc_kernel,
        cudaFuncAttributeMaxDynamicSharedMemorySize, FL_SMEM);

    const int NEL = M_ * D_;
    split_kernel<<<NEL / 4 / 256, 256>>>(x, xhi, xlo, NEL);
    transW_kernel<<<dim3(32, 32, 4), dim3(32, 8)>>>(Wq, Wk, Wv, Wo, wthi, wtlo);

    // Q,K,V projections -> bf16 hi/lo, head-scattered, Q pre-scaled
    gemm_mma_kernel<1><<<dim3(8, 32, 3), 256, GEMM_SMEM>>>(
        xhi, xlo, wthi, wtlo, bq, bk, bv,
        nullptr, qh, ql, kh, kl, vh, vl);

    flash_tc_kernel<<<dim3(S_ / 128, B_ * H_), 256, FL_SMEM>>>(
        qh, ql, kh, kl, vh, vl, ahi, alo);

    gemm_mma_kernel<0><<<dim3(8, 32, 1), 256, GEMM_SMEM>>>(
        ahi, alo, wthi + (size_t)3 * D_ * D_, wtlo + (size_t)3 * D_ * D_,
        bo, bo, bo, out, nullptr, nullptr, nullptr, nullptr, nullptr, nullptr);
}

// round 7
// speedup vs baseline: 3.2023x; 1.1255x over previous
#include <cuda_runtime.h>
#include <cuda_bf16.h>
#include <math.h>
#include <stdint.h>

#define B_ 2
#define S_ 2048
#define D_ 1024
#define H_ 16
#define HD_ 64
#define M_ 4096

// ---------------- scratch (__device__ globals; allocation-free rule) -------
__device__ __nv_bfloat16 g_xhi[M_ * D_];
__device__ __nv_bfloat16 g_xlo[M_ * D_];
__device__ __nv_bfloat16 g_ahi[M_ * D_];
__device__ __nv_bfloat16 g_alo[M_ * D_];
__device__ __nv_bfloat16 g_wthi[4 * D_ * D_];   // W^T as [n][k], bf16 hi
__device__ __nv_bfloat16 g_wtlo[4 * D_ * D_];   // bf16 lo
__device__ __nv_bfloat16 g_qh[M_ * D_];         // [B,H,S,HD] layouts
__device__ __nv_bfloat16 g_ql[M_ * D_];
__device__ __nv_bfloat16 g_kh[M_ * D_];
__device__ __nv_bfloat16 g_kl[M_ * D_];
__device__ __nv_bfloat16 g_vh[M_ * D_];
__device__ __nv_bfloat16 g_vl[M_ * D_];

// ---------------- helpers ---------------------------------------------------
__device__ __forceinline__ uint32_t smem_u32(const void* p) {
    uint32_t a;
    asm("{ .reg .u64 t; cvta.to.shared.u64 t, %1; cvt.u32.u64 %0, t; }"
        : "=r"(a) : "l"(p));
    return a;
}
__device__ __forceinline__ void cp16(uint32_t dst, const void* src) {
    asm volatile("cp.async.cg.shared.global [%0], [%1], 16;" :: "r"(dst), "l"(src));
}
__device__ __forceinline__ void cp_commit() {
    asm volatile("cp.async.commit_group;" ::: "memory");
}
__device__ __forceinline__ void cp_wait1() {
    asm volatile("cp.async.wait_group 1;" ::: "memory");
}
__device__ __forceinline__ void cp_wait0() {
    asm volatile("cp.async.wait_group 0;" ::: "memory");
}
__device__ __forceinline__ void ldsm4(uint32_t* r, uint32_t addr) {
    asm volatile("ldmatrix.sync.aligned.m8n8.x4.shared.b16 {%0,%1,%2,%3}, [%4];"
                 : "=r"(r[0]), "=r"(r[1]), "=r"(r[2]), "=r"(r[3]) : "r"(addr));
}
__device__ __forceinline__ void ldsm4t(uint32_t* r, uint32_t addr) {
    asm volatile("ldmatrix.sync.aligned.m8n8.x4.trans.shared.b16 {%0,%1,%2,%3}, [%4];"
                 : "=r"(r[0]), "=r"(r[1]), "=r"(r[2]), "=r"(r[3]) : "r"(addr));
}
__device__ __forceinline__ void mma16816(float* c, const uint32_t* a,
                                         uint32_t b0, uint32_t b1) {
    asm volatile(
        "mma.sync.aligned.m16n8k16.row.col.f32.bf16.bf16.f32 "
        "{%0,%1,%2,%3}, {%4,%5,%6,%7}, {%8,%9}, {%0,%1,%2,%3};"
        : "+f"(c[0]), "+f"(c[1]), "+f"(c[2]), "+f"(c[3])
        : "r"(a[0]), "r"(a[1]), "r"(a[2]), "r"(a[3]), "r"(b0), "r"(b1));
}
__device__ __forceinline__ float ex2f(float x) {
    float r;
    asm("ex2.approx.ftz.f32 %0, %1;" : "=f"(r) : "f"(x));
    return r;
}
// XOR swizzle: 128B rows of 8 x 16B units
#define SWF(r, c) ((uint32_t)((r) * 128 + ((((c) ^ ((r) & 7))) << 4)))

__device__ __forceinline__ uint32_t pack_bf16_hi(float x, float y,
                                                 float& rx, float& ry) {
    __nv_bfloat16 hx = __float2bfloat16_rn(x);
    __nv_bfloat16 hy = __float2bfloat16_rn(y);
    rx = x - __bfloat162float(hx);
    ry = y - __bfloat162float(hy);
    __nv_bfloat162 p; p.x = hx; p.y = hy;
    return *(uint32_t*)&p;
}
__device__ __forceinline__ uint32_t pack_bf16(float x, float y) {
    __nv_bfloat162 p;
    p.x = __float2bfloat16_rn(x);
    p.y = __float2bfloat16_rn(y);
    return *(uint32_t*)&p;
}

// ---------------------------------------------------------------------------
// Conversion kernels
// ---------------------------------------------------------------------------
__global__ void split_kernel(const float* __restrict__ src,
                             __nv_bfloat16* __restrict__ hi,
                             __nv_bfloat16* __restrict__ lo, int n)
{
    int i = (blockIdx.x * blockDim.x + threadIdx.x) * 4;
    if (i >= n) return;
    float4 v = *(const float4*)(src + i);
    float lx, ly, lz, lw;
    uint32_t h0 = pack_bf16_hi(v.x, v.y, lx, ly);
    uint32_t h1 = pack_bf16_hi(v.z, v.w, lz, lw);
    *(uint32_t*)(hi + i)     = h0;
    *(uint32_t*)(hi + i + 2) = h1;
    *(uint32_t*)(lo + i)     = pack_bf16(lx, ly);
    *(uint32_t*)(lo + i + 2) = pack_bf16(lz, lw);
}

__global__ void transW_kernel(const float* __restrict__ W0, const float* __restrict__ W1,
                              const float* __restrict__ W2, const float* __restrict__ W3,
                              __nv_bfloat16* __restrict__ ohi, __nv_bfloat16* __restrict__ olo)
{
    __shared__ float t[32][33];
    const int z = blockIdx.z;
    const float* W = (z == 0) ? W0 : (z == 1) ? W1 : (z == 2) ? W2 : W3;
    const int n0 = blockIdx.x * 32, k0 = blockIdx.y * 32;
    const int tx = threadIdx.x, ty = threadIdx.y;   // (32,8)
#pragma unroll
    for (int i = 0; i < 4; i++)
        t[ty + 8 * i][tx] = W[(size_t)(k0 + ty + 8 * i) * D_ + n0 + tx];
    __syncthreads();
    __nv_bfloat16* Oh = ohi + (size_t)z * D_ * D_;
    __nv_bfloat16* Ol = olo + (size_t)z * D_ * D_;
#pragma unroll
    for (int i = 0; i < 4; i++) {
        const int n = n0 + ty + 8 * i;
        const int k = k0 + tx;
        const float v = t[tx][ty + 8 * i];
        __nv_bfloat16 h = __float2bfloat16_rn(v);
        Oh[(size_t)n * D_ + k] = h;
        Ol[(size_t)n * D_ + k] = __float2bfloat16_rn(v - __bfloat162float(h));
    }
}

// ---------------------------------------------------------------------------
// mma.sync bf16 GEMM (hi/lo split, 3 terms): C = A @ Wt^T + bias
// CTA 128x128, 256 threads (8 warps 4x2), BK=32, double buffered.
// Fragment-cached inner loop: ldsm once per 16-K slice, 3 mma terms from regs.
// ---------------------------------------------------------------------------
#define BK 32
#define ROWB 80
#define BUF_B (128 * ROWB)
#define STAGE_B (4 * BUF_B)
#define GEMM_SMEM (2 * STAGE_B)
#define LOG2E 1.4426950408889634f

template <int SCATTER>
__global__ __launch_bounds__(256, 2) void gemm_mma_kernel(
    const __nv_bfloat16* __restrict__ Ah, const __nv_bfloat16* __restrict__ Al,
    const __nv_bfloat16* __restrict__ Wth, const __nv_bfloat16* __restrict__ Wtl,
    const float* __restrict__ b0p, const float* __restrict__ b1p,
    const float* __restrict__ b2p,
    float* __restrict__ fo,
    __nv_bfloat16* __restrict__ oh0, __nv_bfloat16* __restrict__ ol0,
    __nv_bfloat16* __restrict__ oh1, __nv_bfloat16* __restrict__ ol1,
    __nv_bfloat16* __restrict__ oh2, __nv_bfloat16* __restrict__ ol2)
{
    extern __shared__ __align__(16) char smem[];
    const uint32_t sbase = smem_u32(smem);
    const int tid  = threadIdx.x;
    const int wid  = tid >> 5;
    const int lane = tid & 31;
    const int wm   = wid & 3;
    const int wn   = wid >> 2;
    const int n0 = blockIdx.x * 128;
    const int m0 = blockIdx.y * 128;
    const int z  = blockIdx.z;

    const __nv_bfloat16* Bh = Wth + (size_t)z * D_ * D_;
    const __nv_bfloat16* Bl = Wtl + (size_t)z * D_ * D_;
    const float* bias = (z == 0) ? b0p : (z == 1) ? b1p : b2p;
    __nv_bfloat16* Ohp = (z == 0) ? oh0 : (z == 1) ? oh1 : oh2;
    __nv_bfloat16* Olp = (z == 0) ? ol0 : (z == 1) ? ol1 : ol2;
    // Q (z==0) pre-scaled by softmax scale folded with log2(e) for exp2 softmax
    const float scl = (SCATTER && z == 0) ? (0.125f * LOG2E) : 1.0f;

    float c[2][8][4];
#pragma unroll
    for (int i = 0; i < 2; i++)
#pragma unroll
        for (int j = 0; j < 8; j++)
#pragma unroll
            for (int q = 0; q < 4; q++) c[i][j][q] = 0.0f;

    const int u0 = tid * 2;
    auto load_chunk = [&](int stage, int kc) {
        const uint32_t sb = sbase + stage * STAGE_B;
#pragma unroll
        for (int u = 0; u < 2; u++) {
            const int idx = u0 + u;
            const int row = idx >> 2;
            const int c4  = idx & 3;
            const uint32_t off = (uint32_t)(row * ROWB + c4 * 16);
            const size_t gA = (size_t)(m0 + row) * D_ + kc * BK + c4 * 8;
            const size_t gB = (size_t)(n0 + row) * D_ + kc * BK + c4 * 8;
            cp16(sb +             off, Ah + gA);
            cp16(sb + 1 * BUF_B + off, Al + gA);
            cp16(sb + 2 * BUF_B + off, Bh + gB);
            cp16(sb + 3 * BUF_B + off, Bl + gB);
        }
        cp_commit();
    };

    const uint32_t a_lane = (uint32_t)((wm * 32 + (lane & 15)) * ROWB + (lane >> 4) * 16);
    const uint32_t b_lane = (uint32_t)((wn * 64 + ((lane >> 4) & 1) * 8 + (lane & 7)) * ROWB
                                       + ((lane >> 3) & 1) * 16);

    const int NCHUNK = D_ / BK;
    load_chunk(0, 0);
    load_chunk(1, 1);

    for (int i = 0; i < NCHUNK; i++) {
        if (i < NCHUNK - 1) cp_wait1(); else cp_wait0();
        __syncthreads();

        const uint32_t stg = sbase + (i & 1) * STAGE_B;
        const uint32_t Abh = stg,              Abl = stg + 1u * BUF_B;
        const uint32_t Bbh = stg + 2u * BUF_B, Bbl = stg + 3u * BUF_B;

#pragma unroll
        for (int kkb = 0; kkb < 2; kkb++) {
            uint32_t ah[2][4], al[2][4];
            ldsm4(ah[0], Abh + a_lane + 0 * 16 * ROWB + kkb * 32);
            ldsm4(ah[1], Abh + a_lane + 1 * 16 * ROWB + kkb * 32);
            ldsm4(al[0], Abl + a_lane + 0 * 16 * ROWB + kkb * 32);
            ldsm4(al[1], Abl + a_lane + 1 * 16 * ROWB + kkb * 32);
#pragma unroll
            for (int half = 0; half < 2; half++) {
                uint32_t bh4[2][4], bl4[2][4];
#pragma unroll
                for (int p = 0; p < 2; p++) {
                    const int np = half * 2 + p;
                    ldsm4(bh4[p], Bbh + b_lane + np * 16 * ROWB + kkb * 32);
                    ldsm4(bl4[p], Bbl + b_lane + np * 16 * ROWB + kkb * 32);
                }
#pragma unroll
                for (int mt = 0; mt < 2; mt++)
#pragma unroll
                    for (int q = 0; q < 4; q++) {
                        const int nt = half * 4 + q;
                        const uint32_t b0h = bh4[q >> 1][(q & 1) * 2];
                        const uint32_t b1h = bh4[q >> 1][(q & 1) * 2 + 1];
                        const uint32_t b0l = bl4[q >> 1][(q & 1) * 2];
                        const uint32_t b1l = bl4[q >> 1][(q & 1) * 2 + 1];
                        float* cc = c[mt][nt];
                        mma16816(cc, ah[mt], b0h, b1h);
                        mma16816(cc, ah[mt], b0l, b1l);
                        mma16816(cc, al[mt], b0h, b1h);
                    }
            }
        }
        __syncthreads();
        if (i + 2 < NCHUNK) load_chunk(i & 1, i + 2);
    }

    const int nb = n0 + wn * 64;
#pragma unroll
    for (int mt = 0; mt < 2; mt++) {
        const int r0 = m0 + wm * 32 + mt * 16 + (lane >> 2);
#pragma unroll
        for (int nt = 0; nt < 8; nt++) {
            const int ng = nb + nt * 8 + (lane & 3) * 2;
            const float bx = bias[ng], by = bias[ng + 1];
            float v0x = (c[mt][nt][0] + bx) * scl, v0y = (c[mt][nt][1] + by) * scl;
            float v1x = (c[mt][nt][2] + bx) * scl, v1y = (c[mt][nt][3] + by) * scl;
            if (SCATTER) {
                const int h = ng >> 6;
                const int dd = ng & 63;
                const int bb0 = r0 >> 11, sI0 = r0 & (S_ - 1);
                const int r1 = r0 + 8;
                const int bb1 = r1 >> 11, sI1 = r1 & (S_ - 1);
                const size_t o0i = ((size_t)(bb0 * H_ + h) * S_ + sI0) * HD_ + dd;
                const size_t o1i = ((size_t)(bb1 * H_ + h) * S_ + sI1) * HD_ + dd;
                float l0x, l0y, l1x, l1y;
                *(uint32_t*)&Ohp[o0i] = pack_bf16_hi(v0x, v0y, l0x, l0y);
                *(uint32_t*)&Olp[o0i] = pack_bf16(l0x, l0y);
                *(uint32_t*)&Ohp[o1i] = pack_bf16_hi(v1x, v1y, l1x, l1y);
                *(uint32_t*)&Olp[o1i] = pack_bf16(l1x, l1y);
            } else {
                *(float2*)&fo[(size_t)r0 * D_ + ng] = make_float2(v0x, v0y);
                *(float2*)&fo[(size_t)(r0 + 8) * D_ + ng] = make_float2(v1x, v1y);
            }
        }
    }
}

// ---------------------------------------------------------------------------
// Tensor-core flash attention (log2-domain online softmax).
// CTA: 128 queries x one (b,h). 8 warps x 16 rows. Key blocks of 64.
// Q pre-scaled by 0.125*log2(e): probabilities via raw ex2.approx.
// ---------------------------------------------------------------------------
#define FL_QBUF 16384                 // 128 rows x 128B
#define FL_KVST 32768                 // 4 bufs x (64 x 128B)
#define FL_SMEM (2 * FL_QBUF + 2 * FL_KVST)   // 96KB

__global__ __launch_bounds__(256) void flash_tc_kernel(
    const __nv_bfloat16* __restrict__ Qh, const __nv_bfloat16* __restrict__ Ql,
    const __nv_bfloat16* __restrict__ Kh, const __nv_bfloat16* __restrict__ Kl,
    const __nv_bfloat16* __restrict__ Vh, const __nv_bfloat16* __restrict__ Vl,
    __nv_bfloat16* __restrict__ Oh, __nv_bfloat16* __restrict__ Ol)
{
    extern __shared__ __align__(16) char smem[];
    const uint32_t base = smem_u32(smem);
    const int tid = threadIdx.x, wid = tid >> 5, lane = tid & 31;
    const int q0 = blockIdx.x * 128;
    const int bh = blockIdx.y;
    const size_t hb = (size_t)bh * S_ * HD_;

#pragma unroll
    for (int u = 0; u < 8; u++) {
        const int idx = tid + u * 256;
        const int bsel = idx >> 10;
        const int r = (idx >> 3) & 127;
        const int c = idx & 7;
        const __nv_bfloat16* src = (bsel ? Ql : Qh) + hb + (size_t)(q0 + r) * HD_ + c * 8;
        cp16(base + bsel * FL_QBUF + SWF(r, c), src);
    }
    cp_commit();

    auto loadkv = [&](int st, int kb) {
        const uint32_t sb = base + 2 * FL_QBUF + st * FL_KVST;
#pragma unroll
        for (int u = 0; u < 8; u++) {
            const int idx = tid + u * 256;
            const int b4 = idx >> 9;
            const int r = (idx >> 3) & 63;
            const int c = idx & 7;
            const __nv_bfloat16* g =
                (b4 == 0) ? Kh : (b4 == 1) ? Kl : (b4 == 2) ? Vh : Vl;
            cp16(sb + b4 * 8192 + SWF(r, c), g + hb + (size_t)(kb * 64 + r) * HD_ + c * 8);
        }
        cp_commit();
    };
    loadkv(0, 0);
    loadkv(1, 1);

    float o[8][4];
#pragma unroll
    for (int nt = 0; nt < 8; nt++)
#pragma unroll
        for (int q = 0; q < 4; q++) o[nt][q] = 0.0f;
    float m0r = -1e30f, m1r = -1e30f, l0 = 0.0f, l1 = 0.0f;

    const int a_row = wid * 16 + (lane & 7) + ((lane >> 3) & 1) * 8;
    const int a_c   = lane >> 4;
    const int k_row = ((lane >> 4) & 1) * 8 + (lane & 7);
    const int k_c   = (lane >> 3) & 1;
    const int v_row = ((lane >> 3) & 1) * 8 + (lane & 7);
    const int v_c   = lane >> 4;

    const int NB = S_ / 64;   // 32
    for (int kb = 0; kb < NB; kb++) {
        if (kb < NB - 1) cp_wait1(); else cp_wait0();
        __syncthreads();
        const uint32_t stg = base + 2 * FL_QBUF + (kb & 1) * FL_KVST;

        // ---- S = Q K^T (3 hi/lo terms); scores already in log2 units ----
        float s[8][4];
#pragma unroll
        for (int nt = 0; nt < 8; nt++)
#pragma unroll
            for (int q = 0; q < 4; q++) s[nt][q] = 0.0f;

#pragma unroll
        for (int ks = 0; ks < 4; ks++) {
            uint32_t ah[4], al[4];
            ldsm4(ah, base +           SWF(a_row, 2 * ks + a_c));
            ldsm4(al, base + FL_QBUF + SWF(a_row, 2 * ks + a_c));
#pragma unroll
            for (int np = 0; np < 4; np++) {
                uint32_t bh4[4], bl4[4];
                ldsm4(bh4, stg +        SWF(np * 16 + k_row, 2 * ks + k_c));
                ldsm4(bl4, stg + 8192 + SWF(np * 16 + k_row, 2 * ks + k_c));
#pragma unroll
                for (int hh = 0; hh < 2; hh++) {
                    float* sc = s[2 * np + hh];
                    mma16816(sc, ah, bh4[2 * hh], bh4[2 * hh + 1]);
                    mma16816(sc, ah, bl4[2 * hh], bl4[2 * hh + 1]);
                    mma16816(sc, al, bh4[2 * hh], bh4[2 * hh + 1]);
                }
            }
        }

        // ---- online softmax in log2 domain ----
        float mx0 = -1e30f, mx1 = -1e30f;
#pragma unroll
        for (int nt = 0; nt < 8; nt++) {
            mx0 = fmaxf(mx0, fmaxf(s[nt][0], s[nt][1]));
            mx1 = fmaxf(mx1, fmaxf(s[nt][2], s[nt][3]));
        }
        mx0 = fmaxf(mx0, __shfl_xor_sync(0xffffffffu, mx0, 1));
        mx0 = fmaxf(mx0, __shfl_xor_sync(0xffffffffu, mx0, 2));
        mx1 = fmaxf(mx1, __shfl_xor_sync(0xffffffffu, mx1, 1));
        mx1 = fmaxf(mx1, __shfl_xor_sync(0xffffffffu, mx1, 2));
        const float mn0 = fmaxf(m0r, mx0);
        const float mn1 = fmaxf(m1r, mx1);
        const float al0 = ex2f(m0r - mn0);
        const float al1 = ex2f(m1r - mn1);
        m0r = mn0; m1r = mn1;

        float sum0 = 0.0f, sum1 = 0.0f;
#pragma unroll
        for (int nt = 0; nt < 8; nt++) {
            s[nt][0] = ex2f(s[nt][0] - mn0);
            s[nt][1] = ex2f(s[nt][1] - mn0);
            s[nt][2] = ex2f(s[nt][2] - mn1);
            s[nt][3] = ex2f(s[nt][3] - mn1);
            sum0 += s[nt][0] + s[nt][1];
            sum1 += s[nt][2] + s[nt][3];
        }
        sum0 += __shfl_xor_sync(0xffffffffu, sum0, 1);
        sum0 += __shfl_xor_sync(0xffffffffu, sum0, 2);
        sum1 += __shfl_xor_sync(0xffffffffu, sum1, 1);
        sum1 += __shfl_xor_sync(0xffffffffu, sum1, 2);
        l0 = l0 * al0 + sum0;
        l1 = l1 * al1 + sum1;
#pragma unroll
        for (int nt = 0; nt < 8; nt++) {
            o[nt][0] *= al0; o[nt][1] *= al0;
            o[nt][2] *= al1; o[nt][3] *= al1;
        }

        // ---- pack P fragments (hi/lo) ----
        uint32_t aph[4][4], apl[4][4];
#pragma unroll
        for (int kc = 0; kc < 4; kc++) {
            float lx, ly;
            aph[kc][0] = pack_bf16_hi(s[2 * kc][0], s[2 * kc][1], lx, ly);
            apl[kc][0] = pack_bf16(lx, ly);
            aph[kc][1] = pack_bf16_hi(s[2 * kc][2], s[2 * kc][3], lx, ly);
            apl[kc][1] = pack_bf16(lx, ly);
            aph[kc][2] = pack_bf16_hi(s[2 * kc + 1][0], s[2 * kc + 1][1], lx, ly);
            apl[kc][2] = pack_bf16(lx, ly);
            aph[kc][3] = pack_bf16_hi(s[2 * kc + 1][2], s[2 * kc + 1][3], lx, ly);
            apl[kc][3] = pack_bf16(lx, ly);
        }

        // ---- O += P V (3 hi/lo terms); V via ldmatrix.trans ----
        const uint32_t vhb = stg + 16384, vlb = stg + 24576;
#pragma unroll
        for (int dp = 0; dp < 4; dp++) {
#pragma unroll
            for (int kc = 0; kc < 4; kc++) {
                uint32_t vh4[4], vl4[4];
                ldsm4t(vh4, vhb + SWF(kc * 16 + v_row, 2 * dp + v_c));
                ldsm4t(vl4, vlb + SWF(kc * 16 + v_row, 2 * dp + v_c));
                mma16816(o[2 * dp],     aph[kc], vh4[0], vh4[1]);
                mma16816(o[2 * dp],     aph[kc], vl4[0], vl4[1]);
                mma16816(o[2 * dp],     apl[kc], vh4[0], vh4[1]);
                mma16816(o[2 * dp + 1], aph[kc], vh4[2], vh4[3]);
                mma16816(o[2 * dp + 1], aph[kc], vl4[2], vl4[3]);
                mma16816(o[2 * dp + 1], apl[kc], vh4[2], vh4[3]);
            }
        }
        __syncthreads();
        if (kb + 2 < NB) loadkv(kb & 1, kb + 2);
    }

    const float inv0 = 1.0f / l0, inv1 = 1.0f / l1;
    const int h = bh & (H_ - 1);
    const int bb = bh >> 4;
    const int r0 = q0 + wid * 16 + (lane >> 2);
    const int r1 = r0 + 8;
#pragma unroll
    for (int nt = 0; nt < 8; nt++) {
        const int gd = h * 64 + nt * 8 + (lane & 3) * 2;
        const size_t i0 = ((size_t)bb * S_ + r0) * D_ + gd;
        const size_t i1 = ((size_t)bb * S_ + r1) * D_ + gd;
        float lx, ly;
        *(uint32_t*)&Oh[i0] = pack_bf16_hi(o[nt][0] * inv0, o[nt][1] * inv0, lx, ly);
        *(uint32_t*)&Ol[i0] = pack_bf16(lx, ly);
        *(uint32_t*)&Oh[i1] = pack_bf16_hi(o[nt][2] * inv1, o[nt][3] * inv1, lx, ly);
        *(uint32_t*)&Ol[i1] = pack_bf16(lx, ly);
    }
}

// ---------------------------------------------------------------------------

extern "C" void kernel_launch(void* const* d_in, const int* in_sizes, int n_in,
                              void* d_out, int out_size)
{
    (void)in_sizes; (void)n_in; (void)out_size;
    const float* x  = (const float*)d_in[0];
    const float* Wq = (const float*)d_in[1];
    const float* bq = (const float*)d_in[2];
    const float* Wk = (const float*)d_in[3];
    const float* bk = (const float*)d_in[4];
    const float* Wv = (const float*)d_in[5];
    const float* bv = (const float*)d_in[6];
    const float* Wo = (const float*)d_in[7];
    const float* bo = (const float*)d_in[8];
    float* out = (float*)d_out;

    __nv_bfloat16 *xhi, *xlo, *ahi, *alo, *wthi, *wtlo;
    __nv_bfloat16 *qh, *ql, *kh, *kl, *vh, *vl;
    cudaGetSymbolAddress((void**)&xhi,  g_xhi);
    cudaGetSymbolAddress((void**)&xlo,  g_xlo);
    cudaGetSymbolAddress((void**)&ahi,  g_ahi);
    cudaGetSymbolAddress((void**)&alo,  g_alo);
    cudaGetSymbolAddress((void**)&wthi, g_wthi);
    cudaGetSymbolAddress((void**)&wtlo, g_wtlo);
    cudaGetSymbolAddress((void**)&qh,   g_qh);
    cudaGetSymbolAddress((void**)&ql,   g_ql);
    cudaGetSymbolAddress((void**)&kh,   g_kh);
    cudaGetSymbolAddress((void**)&kl,   g_kl);
    cudaGetSymbolAddress((void**)&vh,   g_vh);
    cudaGetSymbolAddress((void**)&vl,   g_vl);

    cudaFuncSetAttribute(gemm_mma_kernel<1>,
        cudaFuncAttributeMaxDynamicSharedMemorySize, GEMM_SMEM);
    cudaFuncSetAttribute(gemm_mma_kernel<0>,
        cudaFuncAttributeMaxDynamicSharedMemorySize, GEMM_SMEM);
    cudaFuncSetAttribute(flash_tc_kernel,
        cudaFuncAttributeMaxDynamicSharedMemorySize, FL_SMEM);

    const int NEL = M_ * D_;
    split_kernel<<<NEL / 4 / 256, 256>>>(x, xhi, xlo, NEL);
    transW_kernel<<<dim3(32, 32, 4), dim3(32, 8)>>>(Wq, Wk, Wv, Wo, wthi, wtlo);

    gemm_mma_kernel<1><<<dim3(8, 32, 3), 256, GEMM_SMEM>>>(
        xhi, xlo, wthi, wtlo, bq, bk, bv,
        nullptr, qh, ql, kh, kl, vh, vl);

    flash_tc_kernel<<<dim3(S_ / 128, B_ * H_), 256, FL_SMEM>>>(
        qh, ql, kh, kl, vh, vl, ahi, alo);

    gemm_mma_kernel<0><<<dim3(8, 32, 1), 256, GEMM_SMEM>>>(
        ahi, alo, wthi + (size_t)3 * D_ * D_, wtlo + (size_t)3 * D_ * D_,
        bo, bo, bo, out, nullptr, nullptr, nullptr, nullptr, nullptr, nullptr);
}

// round 8
// speedup vs baseline: 3.3570x; 1.0483x over previous
#include <cuda_runtime.h>
#include <cuda_bf16.h>
#include <math.h>
#include <stdint.h>

#define B_ 2
#define S_ 2048
#define D_ 1024
#define H_ 16
#define HD_ 64
#define M_ 4096

// ---------------- scratch (__device__ globals; allocation-free rule) -------
__device__ __nv_bfloat16 g_xhi[M_ * D_];
__device__ __nv_bfloat16 g_xlo[M_ * D_];
__device__ __nv_bfloat16 g_ahi[M_ * D_];
__device__ __nv_bfloat16 g_alo[M_ * D_];
__device__ __nv_bfloat16 g_wthi[4 * D_ * D_];   // W^T as [n][k], bf16 hi
__device__ __nv_bfloat16 g_wtlo[4 * D_ * D_];   // bf16 lo
__device__ __nv_bfloat16 g_qh[M_ * D_];         // [B,H,S,HD] layouts
__device__ __nv_bfloat16 g_ql[M_ * D_];
__device__ __nv_bfloat16 g_kh[M_ * D_];
__device__ __nv_bfloat16 g_kl[M_ * D_];
__device__ __nv_bfloat16 g_vh[M_ * D_];
__device__ __nv_bfloat16 g_vl[M_ * D_];

// ---------------- helpers ---------------------------------------------------
__device__ __forceinline__ uint32_t smem_u32(const void* p) {
    uint32_t a;
    asm("{ .reg .u64 t; cvta.to.shared.u64 t, %1; cvt.u32.u64 %0, t; }"
        : "=r"(a) : "l"(p));
    return a;
}
__device__ __forceinline__ void cp16(uint32_t dst, const void* src) {
    asm volatile("cp.async.cg.shared.global [%0], [%1], 16;" :: "r"(dst), "l"(src));
}
__device__ __forceinline__ void cp_commit() {
    asm volatile("cp.async.commit_group;" ::: "memory");
}
__device__ __forceinline__ void cp_wait2() {
    asm volatile("cp.async.wait_group 2;" ::: "memory");
}
__device__ __forceinline__ void cp_wait1() {
    asm volatile("cp.async.wait_group 1;" ::: "memory");
}
__device__ __forceinline__ void cp_wait0() {
    asm volatile("cp.async.wait_group 0;" ::: "memory");
}
__device__ __forceinline__ void ldsm4(uint32_t* r, uint32_t addr) {
    asm volatile("ldmatrix.sync.aligned.m8n8.x4.shared.b16 {%0,%1,%2,%3}, [%4];"
                 : "=r"(r[0]), "=r"(r[1]), "=r"(r[2]), "=r"(r[3]) : "r"(addr));
}
__device__ __forceinline__ void ldsm4t(uint32_t* r, uint32_t addr) {
    asm volatile("ldmatrix.sync.aligned.m8n8.x4.trans.shared.b16 {%0,%1,%2,%3}, [%4];"
                 : "=r"(r[0]), "=r"(r[1]), "=r"(r[2]), "=r"(r[3]) : "r"(addr));
}
__device__ __forceinline__ void mma16816(float* c, const uint32_t* a,
                                         uint32_t b0, uint32_t b1) {
    asm volatile(
        "mma.sync.aligned.m16n8k16.row.col.f32.bf16.bf16.f32 "
        "{%0,%1,%2,%3}, {%4,%5,%6,%7}, {%8,%9}, {%0,%1,%2,%3};"
        : "+f"(c[0]), "+f"(c[1]), "+f"(c[2]), "+f"(c[3])
        : "r"(a[0]), "r"(a[1]), "r"(a[2]), "r"(a[3]), "r"(b0), "r"(b1));
}
__device__ __forceinline__ float ex2f(float x) {
    float r;
    asm("ex2.approx.ftz.f32 %0, %1;" : "=f"(r) : "f"(x));
    return r;
}
// XOR swizzle for 128B rows (flash): 8 x 16B units
#define SWF(r, c) ((uint32_t)((r) * 128 + ((((c) ^ ((r) & 7))) << 4)))

__device__ __forceinline__ uint32_t pack_bf16_hi(float x, float y,
                                                 float& rx, float& ry) {
    __nv_bfloat16 hx = __float2bfloat16_rn(x);
    __nv_bfloat16 hy = __float2bfloat16_rn(y);
    rx = x - __bfloat162float(hx);
    ry = y - __bfloat162float(hy);
    __nv_bfloat162 p; p.x = hx; p.y = hy;
    return *(uint32_t*)&p;
}
__device__ __forceinline__ uint32_t pack_bf16(float x, float y) {
    __nv_bfloat162 p;
    p.x = __float2bfloat16_rn(x);
    p.y = __float2bfloat16_rn(y);
    return *(uint32_t*)&p;
}

// ---------------------------------------------------------------------------
// Conversion kernels
// ---------------------------------------------------------------------------
__global__ void split_kernel(const float* __restrict__ src,
                             __nv_bfloat16* __restrict__ hi,
                             __nv_bfloat16* __restrict__ lo, int n)
{
    const int base = blockIdx.x * 4096 + threadIdx.x * 4;
#pragma unroll
    for (int p = 0; p < 4; p++) {
        const int i = base + p * 1024;
        if (i >= n) return;
        float4 v = *(const float4*)(src + i);
        float lx, ly, lz, lw;
        uint32_t h0 = pack_bf16_hi(v.x, v.y, lx, ly);
        uint32_t h1 = pack_bf16_hi(v.z, v.w, lz, lw);
        *(uint32_t*)(hi + i)     = h0;
        *(uint32_t*)(hi + i + 2) = h1;
        *(uint32_t*)(lo + i)     = pack_bf16(lx, ly);
        *(uint32_t*)(lo + i + 2) = pack_bf16(lz, lw);
    }
}

// W [k][n] fp32 -> W^T [n][k] bf16 hi/lo. Tile: 32 k x 64 n. 256 threads.
__global__ void transW_kernel(const float* __restrict__ W0, const float* __restrict__ W1,
                              const float* __restrict__ W2, const float* __restrict__ W3,
                              __nv_bfloat16* __restrict__ ohi, __nv_bfloat16* __restrict__ olo)
{
    __shared__ float t[32][65];
    const int z = blockIdx.z;
    const float* W = (z == 0) ? W0 : (z == 1) ? W1 : (z == 2) ? W2 : W3;
    const int n0 = blockIdx.x * 64, k0 = blockIdx.y * 32;
    const int tid = threadIdx.x;
#pragma unroll
    for (int p = 0; p < 8; p++) {
        const int lin = tid + p * 256;
        const int r = lin >> 6, c = lin & 63;
        t[r][c] = W[(size_t)(k0 + r) * D_ + n0 + c];
    }
    __syncthreads();
    __nv_bfloat16* Oh = ohi + (size_t)z * D_ * D_;
    __nv_bfloat16* Ol = olo + (size_t)z * D_ * D_;
    const int n = n0 + (tid >> 2);
    const int kb = (tid & 3) * 8;
    uint32_t hv[4], lv[4];
#pragma unroll
    for (int j = 0; j < 4; j++) {
        const float vx = t[kb + 2 * j][tid >> 2];
        const float vy = t[kb + 2 * j + 1][tid >> 2];
        float lx, ly;
        hv[j] = pack_bf16_hi(vx, vy, lx, ly);
        lv[j] = pack_bf16(lx, ly);
    }
    *(uint4*)&Oh[(size_t)n * D_ + k0 + kb] = *(uint4*)hv;
    *(uint4*)&Ol[(size_t)n * D_ + k0 + kb] = *(uint4*)lv;
}

// ---------------------------------------------------------------------------
// mma.sync bf16 GEMM (hi/lo split, 3 terms): C = A @ Wt^T + bias
// CTA 128x128, 256 threads (8 warps 4x2), BK=32.
// 64B smem rows, XOR swizzle c^((r>>1)&3), 3-stage cp.async pipeline.
// ---------------------------------------------------------------------------
#define GBUF (128 * 64)          // 8192 B per buffer
#define GSTAGE (4 * GBUF)        // Ah,Al,Bh,Bl = 32768
#define GEMM_SMEM (3 * GSTAGE)   // 98304
#define LOG2E 1.4426950408889634f

template <int SCATTER>
__global__ __launch_bounds__(256, 2) void gemm_mma_kernel(
    const __nv_bfloat16* __restrict__ Ah, const __nv_bfloat16* __restrict__ Al,
    const __nv_bfloat16* __restrict__ Wth, const __nv_bfloat16* __restrict__ Wtl,
    const float* __restrict__ b0p, const float* __restrict__ b1p,
    const float* __restrict__ b2p,
    float* __restrict__ fo,
    __nv_bfloat16* __restrict__ oh0, __nv_bfloat16* __restrict__ ol0,
    __nv_bfloat16* __restrict__ oh1, __nv_bfloat16* __restrict__ ol1,
    __nv_bfloat16* __restrict__ oh2, __nv_bfloat16* __restrict__ ol2)
{
    extern __shared__ __align__(16) char smem[];
    const uint32_t sbase = smem_u32(smem);
    const int tid  = threadIdx.x;
    const int wid  = tid >> 5;
    const int lane = tid & 31;
    const int wm   = wid & 3;
    const int wn   = wid >> 2;
    const int n0 = blockIdx.x * 128;
    const int m0 = blockIdx.y * 128;
    const int z  = blockIdx.z;

    const __nv_bfloat16* Bh = Wth + (size_t)z * D_ * D_;
    const __nv_bfloat16* Bl = Wtl + (size_t)z * D_ * D_;
    const float* bias = (z == 0) ? b0p : (z == 1) ? b1p : b2p;
    __nv_bfloat16* Ohp = (z == 0) ? oh0 : (z == 1) ? oh1 : oh2;
    __nv_bfloat16* Olp = (z == 0) ? ol0 : (z == 1) ? ol1 : ol2;
    const float scl = (SCATTER && z == 0) ? (0.125f * LOG2E) : 1.0f;

    float c[2][8][4];
#pragma unroll
    for (int i = 0; i < 2; i++)
#pragma unroll
        for (int j = 0; j < 8; j++)
#pragma unroll
            for (int q = 0; q < 4; q++) c[i][j][q] = 0.0f;

    // cp.async slice: 2 x 16B per buffer per thread; row = idx>>2, c4 = idx&3
    const int u0 = tid * 2;
    auto load_chunk = [&](int stage, int kc) {
        const uint32_t sb = sbase + stage * GSTAGE;
#pragma unroll
        for (int u = 0; u < 2; u++) {
            const int idx = u0 + u;
            const int row = idx >> 2;
            const int c4  = idx & 3;
            const uint32_t off = (uint32_t)(row * 64 + ((c4 ^ ((row >> 1) & 3)) << 4));
            const size_t gA = (size_t)(m0 + row) * D_ + kc * 32 + c4 * 8;
            const size_t gB = (size_t)(n0 + row) * D_ + kc * 32 + c4 * 8;
            cp16(sb +            off, Ah + gA);
            cp16(sb + 1 * GBUF + off, Al + gA);
            cp16(sb + 2 * GBUF + off, Bh + gB);
            cp16(sb + 3 * GBUF + off, Bl + gB);
        }
        cp_commit();
    };

    // ldsm lane geometry (64B rows, swizzle mask from row>>1)
    const int a_rowb = wm * 32 + (lane & 15);
    const uint32_t a_mask = (uint32_t)(((lane & 15) >> 1) & 3);
    const uint32_t a_cu   = (uint32_t)(lane >> 4);
    const int b_rowb = wn * 64 + ((lane >> 4) & 1) * 8 + (lane & 7);
    const uint32_t b_mask = (uint32_t)(((lane & 7) >> 1) & 3);
    const uint32_t b_cu   = (uint32_t)((lane >> 3) & 1);

    const int NCHUNK = D_ / 32;   // 32
    load_chunk(0, 0);
    load_chunk(1, 1);
    load_chunk(2, 2);

    int st = 0;
    for (int i = 0; i < NCHUNK; i++) {
        if (i < NCHUNK - 2) cp_wait2();
        else if (i == NCHUNK - 2) cp_wait1();
        else cp_wait0();
        __syncthreads();

        const uint32_t stg = sbase + st * GSTAGE;
        const uint32_t Abh = stg,             Abl = stg + 1u * GBUF;
        const uint32_t Bbh = stg + 2u * GBUF, Bbl = stg + 3u * GBUF;

#pragma unroll
        for (int kkb = 0; kkb < 2; kkb++) {
            const uint32_t acsw = (((uint32_t)(kkb * 2) + a_cu) ^ a_mask) << 4;
            const uint32_t bcsw = (((uint32_t)(kkb * 2) + b_cu) ^ b_mask) << 4;
            uint32_t ah[2][4], al[2][4];
            ldsm4(ah[0], Abh + (uint32_t)(a_rowb) * 64 + acsw);
            ldsm4(ah[1], Abh + (uint32_t)(a_rowb + 16) * 64 + acsw);
            ldsm4(al[0], Abl + (uint32_t)(a_rowb) * 64 + acsw);
            ldsm4(al[1], Abl + (uint32_t)(a_rowb + 16) * 64 + acsw);
#pragma unroll
            for (int half = 0; half < 2; half++) {
                uint32_t bh4[2][4], bl4[2][4];
#pragma unroll
                for (int p = 0; p < 2; p++) {
                    const int np = half * 2 + p;
                    ldsm4(bh4[p], Bbh + (uint32_t)(b_rowb + np * 16) * 64 + bcsw);
                    ldsm4(bl4[p], Bbl + (uint32_t)(b_rowb + np * 16) * 64 + bcsw);
                }
#pragma unroll
                for (int mt = 0; mt < 2; mt++)
#pragma unroll
                    for (int q = 0; q < 4; q++) {
                        const int nt = half * 4 + q;
                        const uint32_t b0h = bh4[q >> 1][(q & 1) * 2];
                        const uint32_t b1h = bh4[q >> 1][(q & 1) * 2 + 1];
                        const uint32_t b0l = bl4[q >> 1][(q & 1) * 2];
                        const uint32_t b1l = bl4[q >> 1][(q & 1) * 2 + 1];
                        float* cc = c[mt][nt];
                        mma16816(cc, ah[mt], b0h, b1h);
                        mma16816(cc, ah[mt], b0l, b1l);
                        mma16816(cc, al[mt], b0h, b1h);
                    }
            }
        }
        __syncthreads();
        if (i + 3 < NCHUNK) load_chunk(st, i + 3);
        st = (st == 2) ? 0 : st + 1;
    }

    const int nb = n0 + wn * 64;
#pragma unroll
    for (int mt = 0; mt < 2; mt++) {
        const int r0 = m0 + wm * 32 + mt * 16 + (lane >> 2);
#pragma unroll
        for (int nt = 0; nt < 8; nt++) {
            const int ng = nb + nt * 8 + (lane & 3) * 2;
            const float bx = bias[ng], by = bias[ng + 1];
            float v0x = (c[mt][nt][0] + bx) * scl, v0y = (c[mt][nt][1] + by) * scl;
            float v1x = (c[mt][nt][2] + bx) * scl, v1y = (c[mt][nt][3] + by) * scl;
            if (SCATTER) {
                const int h = ng >> 6;
                const int dd = ng & 63;
                const int bb0 = r0 >> 11, sI0 = r0 & (S_ - 1);
                const int r1 = r0 + 8;
                const int bb1 = r1 >> 11, sI1 = r1 & (S_ - 1);
                const size_t o0i = ((size_t)(bb0 * H_ + h) * S_ + sI0) * HD_ + dd;
                const size_t o1i = ((size_t)(bb1 * H_ + h) * S_ + sI1) * HD_ + dd;
                float l0x, l0y, l1x, l1y;
                *(uint32_t*)&Ohp[o0i] = pack_bf16_hi(v0x, v0y, l0x, l0y);
                *(uint32_t*)&Olp[o0i] = pack_bf16(l0x, l0y);
                *(uint32_t*)&Ohp[o1i] = pack_bf16_hi(v1x, v1y, l1x, l1y);
                *(uint32_t*)&Olp[o1i] = pack_bf16(l1x, l1y);
            } else {
                *(float2*)&fo[(size_t)r0 * D_ + ng] = make_float2(v0x, v0y);
                *(float2*)&fo[(size_t)(r0 + 8) * D_ + ng] = make_float2(v1x, v1y);
            }
        }
    }
}

// ---------------------------------------------------------------------------
// Tensor-core flash attention (log2-domain online softmax). Unchanged from R7.
// ---------------------------------------------------------------------------
#define FL_QBUF 16384
#define FL_KVST 32768
#define FL_SMEM (2 * FL_QBUF + 2 * FL_KVST)   // 96KB

__global__ __launch_bounds__(256) void flash_tc_kernel(
    const __nv_bfloat16* __restrict__ Qh, const __nv_bfloat16* __restrict__ Ql,
    const __nv_bfloat16* __restrict__ Kh, const __nv_bfloat16* __restrict__ Kl,
    const __nv_bfloat16* __restrict__ Vh, const __nv_bfloat16* __restrict__ Vl,
    __nv_bfloat16* __restrict__ Oh, __nv_bfloat16* __restrict__ Ol)
{
    extern __shared__ __align__(16) char smem[];
    const uint32_t base = smem_u32(smem);
    const int tid = threadIdx.x, wid = tid >> 5, lane = tid & 31;
    const int q0 = blockIdx.x * 128;
    const int bh = blockIdx.y;
    const size_t hb = (size_t)bh * S_ * HD_;

#pragma unroll
    for (int u = 0; u < 8; u++) {
        const int idx = tid + u * 256;
        const int bsel = idx >> 10;
        const int r = (idx >> 3) & 127;
        const int c = idx & 7;
        const __nv_bfloat16* src = (bsel ? Ql : Qh) + hb + (size_t)(q0 + r) * HD_ + c * 8;
        cp16(base + bsel * FL_QBUF + SWF(r, c), src);
    }
    cp_commit();

    auto loadkv = [&](int st, int kb) {
        const uint32_t sb = base + 2 * FL_QBUF + st * FL_KVST;
#pragma unroll
        for (int u = 0; u < 8; u++) {
            const int idx = tid + u * 256;
            const int b4 = idx >> 9;
            const int r = (idx >> 3) & 63;
            const int c = idx & 7;
            const __nv_bfloat16* g =
                (b4 == 0) ? Kh : (b4 == 1) ? Kl : (b4 == 2) ? Vh : Vl;
            cp16(sb + b4 * 8192 + SWF(r, c), g + hb + (size_t)(kb * 64 + r) * HD_ + c * 8);
        }
        cp_commit();
    };
    loadkv(0, 0);
    loadkv(1, 1);

    float o[8][4];
#pragma unroll
    for (int nt = 0; nt < 8; nt++)
#pragma unroll
        for (int q = 0; q < 4; q++) o[nt][q] = 0.0f;
    float m0r = -1e30f, m1r = -1e30f, l0 = 0.0f, l1 = 0.0f;

    const int a_row = wid * 16 + (lane & 7) + ((lane >> 3) & 1) * 8;
    const int a_c   = lane >> 4;
    const int k_row = ((lane >> 4) & 1) * 8 + (lane & 7);
    const int k_c   = (lane >> 3) & 1;
    const int v_row = ((lane >> 3) & 1) * 8 + (lane & 7);
    const int v_c   = lane >> 4;

    const int NB = S_ / 64;   // 32
    for (int kb = 0; kb < NB; kb++) {
        if (kb < NB - 1) cp_wait1(); else cp_wait0();
        __syncthreads();
        const uint32_t stg = base + 2 * FL_QBUF + (kb & 1) * FL_KVST;

        float s[8][4];
#pragma unroll
        for (int nt = 0; nt < 8; nt++)
#pragma unroll
            for (int q = 0; q < 4; q++) s[nt][q] = 0.0f;

#pragma unroll
        for (int ks = 0; ks < 4; ks++) {
            uint32_t ah[4], al[4];
            ldsm4(ah, base +           SWF(a_row, 2 * ks + a_c));
            ldsm4(al, base + FL_QBUF + SWF(a_row, 2 * ks + a_c));
#pragma unroll
            for (int np = 0; np < 4; np++) {
                uint32_t bh4[4], bl4[4];
                ldsm4(bh4, stg +        SWF(np * 16 + k_row, 2 * ks + k_c));
                ldsm4(bl4, stg + 8192 + SWF(np * 16 + k_row, 2 * ks + k_c));
#pragma unroll
                for (int hh = 0; hh < 2; hh++) {
                    float* sc = s[2 * np + hh];
                    mma16816(sc, ah, bh4[2 * hh], bh4[2 * hh + 1]);
                    mma16816(sc, ah, bl4[2 * hh], bl4[2 * hh + 1]);
                    mma16816(sc, al, bh4[2 * hh], bh4[2 * hh + 1]);
                }
            }
        }

        float mx0 = -1e30f, mx1 = -1e30f;
#pragma unroll
        for (int nt = 0; nt < 8; nt++) {
            mx0 = fmaxf(mx0, fmaxf(s[nt][0], s[nt][1]));
            mx1 = fmaxf(mx1, fmaxf(s[nt][2], s[nt][3]));
        }
        mx0 = fmaxf(mx0, __shfl_xor_sync(0xffffffffu, mx0, 1));
        mx0 = fmaxf(mx0, __shfl_xor_sync(0xffffffffu, mx0, 2));
        mx1 = fmaxf(mx1, __shfl_xor_sync(0xffffffffu, mx1, 1));
        mx1 = fmaxf(mx1, __shfl_xor_sync(0xffffffffu, mx1, 2));
        const float mn0 = fmaxf(m0r, mx0);
        const float mn1 = fmaxf(m1r, mx1);
        const float al0 = ex2f(m0r - mn0);
        const float al1 = ex2f(m1r - mn1);
        m0r = mn0; m1r = mn1;

        float sum0 = 0.0f, sum1 = 0.0f;
#pragma unroll
        for (int nt = 0; nt < 8; nt++) {
            s[nt][0] = ex2f(s[nt][0] - mn0);
            s[nt][1] = ex2f(s[nt][1] - mn0);
            s[nt][2] = ex2f(s[nt][2] - mn1);
            s[nt][3] = ex2f(s[nt][3] - mn1);
            sum0 += s[nt][0] + s[nt][1];
            sum1 += s[nt][2] + s[nt][3];
        }
        sum0 += __shfl_xor_sync(0xffffffffu, sum0, 1);
        sum0 += __shfl_xor_sync(0xffffffffu, sum0, 2);
        sum1 += __shfl_xor_sync(0xffffffffu, sum1, 1);
        sum1 += __shfl_xor_sync(0xffffffffu, sum1, 2);
        l0 = l0 * al0 + sum0;
        l1 = l1 * al1 + sum1;
#pragma unroll
        for (int nt = 0; nt < 8; nt++) {
            o[nt][0] *= al0; o[nt][1] *= al0;
            o[nt][2] *= al1; o[nt][3] *= al1;
        }

        uint32_t aph[4][4], apl[4][4];
#pragma unroll
        for (int kc = 0; kc < 4; kc++) {
            float lx, ly;
            aph[kc][0] = pack_bf16_hi(s[2 * kc][0], s[2 * kc][1], lx, ly);
            apl[kc][0] = pack_bf16(lx, ly);
            aph[kc][1] = pack_bf16_hi(s[2 * kc][2], s[2 * kc][3], lx, ly);
            apl[kc][1] = pack_bf16(lx, ly);
            aph[kc][2] = pack_bf16_hi(s[2 * kc + 1][0], s[2 * kc + 1][1], lx, ly);
            apl[kc][2] = pack_bf16(lx, ly);
            aph[kc][3] = pack_bf16_hi(s[2 * kc + 1][2], s[2 * kc + 1][3], lx, ly);
            apl[kc][3] = pack_bf16(lx, ly);
        }

        const uint32_t vhb = stg + 16384, vlb = stg + 24576;
#pragma unroll
        for (int dp = 0; dp < 4; dp++) {
#pragma unroll
            for (int kc = 0; kc < 4; kc++) {
                uint32_t vh4[4], vl4[4];
                ldsm4t(vh4, vhb + SWF(kc * 16 + v_row, 2 * dp + v_c));
                ldsm4t(vl4, vlb + SWF(kc * 16 + v_row, 2 * dp + v_c));
                mma16816(o[2 * dp],     aph[kc], vh4[0], vh4[1]);
                mma16816(o[2 * dp],     aph[kc], vl4[0], vl4[1]);
                mma16816(o[2 * dp],     apl[kc], vh4[0], vh4[1]);
                mma16816(o[2 * dp + 1], aph[kc], vh4[2], vh4[3]);
                mma16816(o[2 * dp + 1], aph[kc], vl4[2], vl4[3]);
                mma16816(o[2 * dp + 1], apl[kc], vh4[2], vh4[3]);
            }
        }
        __syncthreads();
        if (kb + 2 < NB) loadkv(kb & 1, kb + 2);
    }

    const float inv0 = 1.0f / l0, inv1 = 1.0f / l1;
    const int h = bh & (H_ - 1);
    const int bb = bh >> 4;
    const int r0 = q0 + wid * 16 + (lane >> 2);
    const int r1 = r0 + 8;
#pragma unroll
    for (int nt = 0; nt < 8; nt++) {
        const int gd = h * 64 + nt * 8 + (lane & 3) * 2;
        const size_t i0 = ((size_t)bb * S_ + r0) * D_ + gd;
        const size_t i1 = ((size_t)bb * S_ + r1) * D_ + gd;
        float lx, ly;
        *(uint32_t*)&Oh[i0] = pack_bf16_hi(o[nt][0] * inv0, o[nt][1] * inv0, lx, ly);
        *(uint32_t*)&Ol[i0] = pack_bf16(lx, ly);
        *(uint32_t*)&Oh[i1] = pack_bf16_hi(o[nt][2] * inv1, o[nt][3] * inv1, lx, ly);
        *(uint32_t*)&Ol[i1] = pack_bf16(lx, ly);
    }
}

// ---------------------------------------------------------------------------

extern "C" void kernel_launch(void* const* d_in, const int* in_sizes, int n_in,
                              void* d_out, int out_size)
{
    (void)in_sizes; (void)n_in; (void)out_size;
    const float* x  = (const float*)d_in[0];
    const float* Wq = (const float*)d_in[1];
    const float* bq = (const float*)d_in[2];
    const float* Wk = (const float*)d_in[3];
    const float* bk = (const float*)d_in[4];
    const float* Wv = (const float*)d_in[5];
    const float* bv = (const float*)d_in[6];
    const float* Wo = (const float*)d_in[7];
    const float* bo = (const float*)d_in[8];
    float* out = (float*)d_out;

    __nv_bfloat16 *xhi, *xlo, *ahi, *alo, *wthi, *wtlo;
    __nv_bfloat16 *qh, *ql, *kh, *kl, *vh, *vl;
    cudaGetSymbolAddress((void**)&xhi,  g_xhi);
    cudaGetSymbolAddress((void**)&xlo,  g_xlo);
    cudaGetSymbolAddress((void**)&ahi,  g_ahi);
    cudaGetSymbolAddress((void**)&alo,  g_alo);
    cudaGetSymbolAddress((void**)&wthi, g_wthi);
    cudaGetSymbolAddress((void**)&wtlo, g_wtlo);
    cudaGetSymbolAddress((void**)&qh,   g_qh);
    cudaGetSymbolAddress((void**)&ql,   g_ql);
    cudaGetSymbolAddress((void**)&kh,   g_kh);
    cudaGetSymbolAddress((void**)&kl,   g_kl);
    cudaGetSymbolAddress((void**)&vh,   g_vh);
    cudaGetSymbolAddress((void**)&vl,   g_vl);

    cudaFuncSetAttribute(gemm_mma_kernel<1>,
        cudaFuncAttributeMaxDynamicSharedMemorySize, GEMM_SMEM);
    cudaFuncSetAttribute(gemm_mma_kernel<0>,
        cudaFuncAttributeMaxDynamicSharedMemorySize, GEMM_SMEM);
    cudaFuncSetAttribute(flash_tc_kernel,
        cudaFuncAttributeMaxDynamicSharedMemorySize, FL_SMEM);

    const int NEL = M_ * D_;
    split_kernel<<<NEL / 4096, 256>>>(x, xhi, xlo, NEL);
    transW_kernel<<<dim3(16, 32, 4), 256>>>(Wq, Wk, Wv, Wo, wthi, wtlo);

    gemm_mma_kernel<1><<<dim3(8, 32, 3), 256, GEMM_SMEM>>>(
        xhi, xlo, wthi, wtlo, bq, bk, bv,
        nullptr, qh, ql, kh, kl, vh, vl);

    flash_tc_kernel<<<dim3(S_ / 128, B_ * H_), 256, FL_SMEM>>>(
        qh, ql, kh, kl, vh, vl, ahi, alo);

    gemm_mma_kernel<0><<<dim3(8, 32, 1), 256, GEMM_SMEM>>>(
        ahi, alo, wthi + (size_t)3 * D_ * D_, wtlo + (size_t)3 * D_ * D_,
        bo, bo, bo, out, nullptr, nullptr, nullptr, nullptr, nullptr, nullptr);
}

// round 9
// speedup vs baseline: 3.6481x; 1.0867x over previous
#include <cuda_runtime.h>
#include <cuda_bf16.h>
#include <cuda_fp16.h>
#include <math.h>
#include <stdint.h>

#define B_ 2
#define S_ 2048
#define D_ 1024
#define H_ 16
#define HD_ 64
#define M_ 4096

// ---------------- scratch (__device__ globals; allocation-free rule) -------
__device__ __nv_bfloat16 g_xhi[M_ * D_];
__device__ __nv_bfloat16 g_xlo[M_ * D_];
__device__ __nv_bfloat16 g_ahi[M_ * D_];
__device__ __nv_bfloat16 g_alo[M_ * D_];
__device__ __nv_bfloat16 g_wthi[4 * D_ * D_];   // W^T as [n][k], bf16 hi
__device__ __nv_bfloat16 g_wtlo[4 * D_ * D_];   // bf16 lo
__device__ __nv_bfloat16 g_qh[M_ * D_];         // [B,H,S,HD] layouts
__device__ __nv_bfloat16 g_ql[M_ * D_];
__device__ __nv_bfloat16 g_kh[M_ * D_];
__device__ __nv_bfloat16 g_kl[M_ * D_];
__device__ __half        g_vh[M_ * D_];         // V in fp16 hi/lo
__device__ __half        g_vl[M_ * D_];

// ---------------- helpers ---------------------------------------------------
__device__ __forceinline__ uint32_t smem_u32(const void* p) {
    uint32_t a;
    asm("{ .reg .u64 t; cvta.to.shared.u64 t, %1; cvt.u32.u64 %0, t; }"
        : "=r"(a) : "l"(p));
    return a;
}
__device__ __forceinline__ void cp16(uint32_t dst, const void* src) {
    asm volatile("cp.async.cg.shared.global [%0], [%1], 16;" :: "r"(dst), "l"(src));
}
__device__ __forceinline__ void cp_commit() {
    asm volatile("cp.async.commit_group;" ::: "memory");
}
__device__ __forceinline__ void cp_wait2() {
    asm volatile("cp.async.wait_group 2;" ::: "memory");
}
__device__ __forceinline__ void cp_wait1() {
    asm volatile("cp.async.wait_group 1;" ::: "memory");
}
__device__ __forceinline__ void cp_wait0() {
    asm volatile("cp.async.wait_group 0;" ::: "memory");
}
__device__ __forceinline__ void ldsm4(uint32_t* r, uint32_t addr) {
    asm volatile("ldmatrix.sync.aligned.m8n8.x4.shared.b16 {%0,%1,%2,%3}, [%4];"
                 : "=r"(r[0]), "=r"(r[1]), "=r"(r[2]), "=r"(r[3]) : "r"(addr));
}
__device__ __forceinline__ void ldsm4t(uint32_t* r, uint32_t addr) {
    asm volatile("ldmatrix.sync.aligned.m8n8.x4.trans.shared.b16 {%0,%1,%2,%3}, [%4];"
                 : "=r"(r[0]), "=r"(r[1]), "=r"(r[2]), "=r"(r[3]) : "r"(addr));
}
__device__ __forceinline__ void mma16816(float* c, const uint32_t* a,
                                         uint32_t b0, uint32_t b1) {
    asm volatile(
        "mma.sync.aligned.m16n8k16.row.col.f32.bf16.bf16.f32 "
        "{%0,%1,%2,%3}, {%4,%5,%6,%7}, {%8,%9}, {%0,%1,%2,%3};"
        : "+f"(c[0]), "+f"(c[1]), "+f"(c[2]), "+f"(c[3])
        : "r"(a[0]), "r"(a[1]), "r"(a[2]), "r"(a[3]), "r"(b0), "r"(b1));
}
__device__ __forceinline__ void mma16816h(float* c, const uint32_t* a,
                                          uint32_t b0, uint32_t b1) {
    asm volatile(
        "mma.sync.aligned.m16n8k16.row.col.f32.f16.f16.f32 "
        "{%0,%1,%2,%3}, {%4,%5,%6,%7}, {%8,%9}, {%0,%1,%2,%3};"
        : "+f"(c[0]), "+f"(c[1]), "+f"(c[2]), "+f"(c[3])
        : "r"(a[0]), "r"(a[1]), "r"(a[2]), "r"(a[3]), "r"(b0), "r"(b1));
}
__device__ __forceinline__ float ex2f(float x) {
    float r;
    asm("ex2.approx.ftz.f32 %0, %1;" : "=f"(r) : "f"(x));
    return r;
}
// XOR swizzle for 128B rows (flash): 8 x 16B units
#define SWF(r, c) ((uint32_t)((r) * 128 + ((((c) ^ ((r) & 7))) << 4)))

__device__ __forceinline__ uint32_t pack_bf16_hi(float x, float y,
                                                 float& rx, float& ry) {
    __nv_bfloat16 hx = __float2bfloat16_rn(x);
    __nv_bfloat16 hy = __float2bfloat16_rn(y);
    rx = x - __bfloat162float(hx);
    ry = y - __bfloat162float(hy);
    __nv_bfloat162 p; p.x = hx; p.y = hy;
    return *(uint32_t*)&p;
}
__device__ __forceinline__ uint32_t pack_bf16(float x, float y) {
    __nv_bfloat162 p;
    p.x = __float2bfloat16_rn(x);
    p.y = __float2bfloat16_rn(y);
    return *(uint32_t*)&p;
}
__device__ __forceinline__ uint32_t pack_f16_hi(float x, float y,
                                                float& rx, float& ry) {
    __half hx = __float2half_rn(x);
    __half hy = __float2half_rn(y);
    rx = x - __half2float(hx);
    ry = y - __half2float(hy);
    __half2 p; p.x = hx; p.y = hy;
    return *(uint32_t*)&p;
}
__device__ __forceinline__ uint32_t pack_f16(float x, float y) {
    __half2 p = __floats2half2_rn(x, y);
    return *(uint32_t*)&p;
}

// ---------------------------------------------------------------------------
// Conversion kernels
// ---------------------------------------------------------------------------
__global__ void split_kernel(const float* __restrict__ src,
                             __nv_bfloat16* __restrict__ hi,
                             __nv_bfloat16* __restrict__ lo, int n)
{
    const int base = blockIdx.x * 4096 + threadIdx.x * 4;
#pragma unroll
    for (int p = 0; p < 4; p++) {
        const int i = base + p * 1024;
        if (i >= n) return;
        float4 v = *(const float4*)(src + i);
        float lx, ly, lz, lw;
        uint32_t h0 = pack_bf16_hi(v.x, v.y, lx, ly);
        uint32_t h1 = pack_bf16_hi(v.z, v.w, lz, lw);
        *(uint32_t*)(hi + i)     = h0;
        *(uint32_t*)(hi + i + 2) = h1;
        *(uint32_t*)(lo + i)     = pack_bf16(lx, ly);
        *(uint32_t*)(lo + i + 2) = pack_bf16(lz, lw);
    }
}

// W [k][n] fp32 -> W^T [n][k] bf16 hi/lo. Tile: 32 k x 64 n. 256 threads.
__global__ void transW_kernel(const float* __restrict__ W0, const float* __restrict__ W1,
                              const float* __restrict__ W2, const float* __restrict__ W3,
                              __nv_bfloat16* __restrict__ ohi, __nv_bfloat16* __restrict__ olo)
{
    __shared__ float t[32][65];
    const int z = blockIdx.z;
    const float* W = (z == 0) ? W0 : (z == 1) ? W1 : (z == 2) ? W2 : W3;
    const int n0 = blockIdx.x * 64, k0 = blockIdx.y * 32;
    const int tid = threadIdx.x;
#pragma unroll
    for (int p = 0; p < 8; p++) {
        const int lin = tid + p * 256;
        const int r = lin >> 6, c = lin & 63;
        t[r][c] = W[(size_t)(k0 + r) * D_ + n0 + c];
    }
    __syncthreads();
    __nv_bfloat16* Oh = ohi + (size_t)z * D_ * D_;
    __nv_bfloat16* Ol = olo + (size_t)z * D_ * D_;
    const int n = n0 + (tid >> 2);
    const int kb = (tid & 3) * 8;
    uint32_t hv[4], lv[4];
#pragma unroll
    for (int j = 0; j < 4; j++) {
        const float vx = t[kb + 2 * j][tid >> 2];
        const float vy = t[kb + 2 * j + 1][tid >> 2];
        float lx, ly;
        hv[j] = pack_bf16_hi(vx, vy, lx, ly);
        lv[j] = pack_bf16(lx, ly);
    }
    *(uint4*)&Oh[(size_t)n * D_ + k0 + kb] = *(uint4*)hv;
    *(uint4*)&Ol[(size_t)n * D_ + k0 + kb] = *(uint4*)lv;
}

// ---------------------------------------------------------------------------
// mma.sync bf16 GEMM (hi/lo split, 3 terms): C = A @ Wt^T + bias
// CTA 128x128, 256 threads (8 warps 4x2), BK=32.
// 64B smem rows, XOR swizzle, 3-stage cp.async pipeline.
// SCATTER: z==0 Q (bf16, pre-scaled), z==1 K (bf16), z==2 V (fp16 hi/lo).
// ---------------------------------------------------------------------------
#define GBUF (128 * 64)
#define GSTAGE (4 * GBUF)
#define GEMM_SMEM (3 * GSTAGE)
#define LOG2E 1.4426950408889634f

template <int SCATTER>
__global__ __launch_bounds__(256, 2) void gemm_mma_kernel(
    const __nv_bfloat16* __restrict__ Ah, const __nv_bfloat16* __restrict__ Al,
    const __nv_bfloat16* __restrict__ Wth, const __nv_bfloat16* __restrict__ Wtl,
    const float* __restrict__ b0p, const float* __restrict__ b1p,
    const float* __restrict__ b2p,
    float* __restrict__ fo,
    __nv_bfloat16* __restrict__ oh0, __nv_bfloat16* __restrict__ ol0,
    __nv_bfloat16* __restrict__ oh1, __nv_bfloat16* __restrict__ ol1,
    __half* __restrict__ oh2, __half* __restrict__ ol2)
{
    extern __shared__ __align__(16) char smem[];
    const uint32_t sbase = smem_u32(smem);
    const int tid  = threadIdx.x;
    const int wid  = tid >> 5;
    const int lane = tid & 31;
    const int wm   = wid & 3;
    const int wn   = wid >> 2;
    const int n0 = blockIdx.x * 128;
    const int m0 = blockIdx.y * 128;
    const int z  = blockIdx.z;

    const __nv_bfloat16* Bh = Wth + (size_t)z * D_ * D_;
    const __nv_bfloat16* Bl = Wtl + (size_t)z * D_ * D_;
    const float* bias = (z == 0) ? b0p : (z == 1) ? b1p : b2p;
    __nv_bfloat16* Ohp = (z == 0) ? oh0 : oh1;
    __nv_bfloat16* Olp = (z == 0) ? ol0 : ol1;
    const float scl = (SCATTER && z == 0) ? (0.125f * LOG2E) : 1.0f;

    float c[2][8][4];
#pragma unroll
    for (int i = 0; i < 2; i++)
#pragma unroll
        for (int j = 0; j < 8; j++)
#pragma unroll
            for (int q = 0; q < 4; q++) c[i][j][q] = 0.0f;

    const int u0 = tid * 2;
    auto load_chunk = [&](int stage, int kc) {
        const uint32_t sb = sbase + stage * GSTAGE;
#pragma unroll
        for (int u = 0; u < 2; u++) {
            const int idx = u0 + u;
            const int row = idx >> 2;
            const int c4  = idx & 3;
            const uint32_t off = (uint32_t)(row * 64 + ((c4 ^ ((row >> 1) & 3)) << 4));
            const size_t gA = (size_t)(m0 + row) * D_ + kc * 32 + c4 * 8;
            const size_t gB = (size_t)(n0 + row) * D_ + kc * 32 + c4 * 8;
            cp16(sb +            off, Ah + gA);
            cp16(sb + 1 * GBUF + off, Al + gA);
            cp16(sb + 2 * GBUF + off, Bh + gB);
            cp16(sb + 3 * GBUF + off, Bl + gB);
        }
        cp_commit();
    };

    const int a_rowb = wm * 32 + (lane & 15);
    const uint32_t a_mask = (uint32_t)(((lane & 15) >> 1) & 3);
    const uint32_t a_cu   = (uint32_t)(lane >> 4);
    const int b_rowb = wn * 64 + ((lane >> 4) & 1) * 8 + (lane & 7);
    const uint32_t b_mask = (uint32_t)(((lane & 7) >> 1) & 3);
    const uint32_t b_cu   = (uint32_t)((lane >> 3) & 1);

    const int NCHUNK = D_ / 32;
    load_chunk(0, 0);
    load_chunk(1, 1);
    load_chunk(2, 2);

    int st = 0;
    for (int i = 0; i < NCHUNK; i++) {
        if (i < NCHUNK - 2) cp_wait2();
        else if (i == NCHUNK - 2) cp_wait1();
        else cp_wait0();
        __syncthreads();

        const uint32_t stg = sbase + st * GSTAGE;
        const uint32_t Abh = stg,             Abl = stg + 1u * GBUF;
        const uint32_t Bbh = stg + 2u * GBUF, Bbl = stg + 3u * GBUF;

#pragma unroll
        for (int kkb = 0; kkb < 2; kkb++) {
            const uint32_t acsw = (((uint32_t)(kkb * 2) + a_cu) ^ a_mask) << 4;
            const uint32_t bcsw = (((uint32_t)(kkb * 2) + b_cu) ^ b_mask) << 4;
            uint32_t ah[2][4], al[2][4];
            ldsm4(ah[0], Abh + (uint32_t)(a_rowb) * 64 + acsw);
            ldsm4(ah[1], Abh + (uint32_t)(a_rowb + 16) * 64 + acsw);
            ldsm4(al[0], Abl + (uint32_t)(a_rowb) * 64 + acsw);
            ldsm4(al[1], Abl + (uint32_t)(a_rowb + 16) * 64 + acsw);
#pragma unroll
            for (int half = 0; half < 2; half++) {
                uint32_t bh4[2][4], bl4[2][4];
#pragma unroll
                for (int p = 0; p < 2; p++) {
                    const int np = half * 2 + p;
                    ldsm4(bh4[p], Bbh + (uint32_t)(b_rowb + np * 16) * 64 + bcsw);
                    ldsm4(bl4[p], Bbl + (uint32_t)(b_rowb + np * 16) * 64 + bcsw);
                }
#pragma unroll
                for (int mt = 0; mt < 2; mt++)
#pragma unroll
                    for (int q = 0; q < 4; q++) {
                        const int nt = half * 4 + q;
                        const uint32_t b0h = bh4[q >> 1][(q & 1) * 2];
                        const uint32_t b1h = bh4[q >> 1][(q & 1) * 2 + 1];
                        const uint32_t b0l = bl4[q >> 1][(q & 1) * 2];
                        const uint32_t b1l = bl4[q >> 1][(q & 1) * 2 + 1];
                        float* cc = c[mt][nt];
                        mma16816(cc, ah[mt], b0h, b1h);
                        mma16816(cc, ah[mt], b0l, b1l);
                        mma16816(cc, al[mt], b0h, b1h);
                    }
            }
        }
        __syncthreads();
        if (i + 3 < NCHUNK) load_chunk(st, i + 3);
        st = (st == 2) ? 0 : st + 1;
    }

    const int nb = n0 + wn * 64;
#pragma unroll
    for (int mt = 0; mt < 2; mt++) {
        const int r0 = m0 + wm * 32 + mt * 16 + (lane >> 2);
#pragma unroll
        for (int nt = 0; nt < 8; nt++) {
            const int ng = nb + nt * 8 + (lane & 3) * 2;
            const float bx = bias[ng], by = bias[ng + 1];
            float v0x = (c[mt][nt][0] + bx) * scl, v0y = (c[mt][nt][1] + by) * scl;
            float v1x = (c[mt][nt][2] + bx) * scl, v1y = (c[mt][nt][3] + by) * scl;
            if (SCATTER) {
                const int h = ng >> 6;
                const int dd = ng & 63;
                const int bb0 = r0 >> 11, sI0 = r0 & (S_ - 1);
                const int r1 = r0 + 8;
                const int bb1 = r1 >> 11, sI1 = r1 & (S_ - 1);
                const size_t o0i = ((size_t)(bb0 * H_ + h) * S_ + sI0) * HD_ + dd;
                const size_t o1i = ((size_t)(bb1 * H_ + h) * S_ + sI1) * HD_ + dd;
                float l0x, l0y, l1x, l1y;
                if (z == 2) {   // V: fp16 hi/lo
                    *(uint32_t*)&oh2[o0i] = pack_f16_hi(v0x, v0y, l0x, l0y);
                    *(uint32_t*)&ol2[o0i] = pack_f16(l0x, l0y);
                    *(uint32_t*)&oh2[o1i] = pack_f16_hi(v1x, v1y, l1x, l1y);
                    *(uint32_t*)&ol2[o1i] = pack_f16(l1x, l1y);
                } else {        // Q/K: bf16 hi/lo
                    *(uint32_t*)&Ohp[o0i] = pack_bf16_hi(v0x, v0y, l0x, l0y);
                    *(uint32_t*)&Olp[o0i] = pack_bf16(l0x, l0y);
                    *(uint32_t*)&Ohp[o1i] = pack_bf16_hi(v1x, v1y, l1x, l1y);
                    *(uint32_t*)&Olp[o1i] = pack_bf16(l1x, l1y);
                }
            } else {
                *(float2*)&fo[(size_t)r0 * D_ + ng] = make_float2(v0x, v0y);
                *(float2*)&fo[(size_t)(r0 + 8) * D_ + ng] = make_float2(v1x, v1y);
            }
        }
    }
}

// ---------------------------------------------------------------------------
// Tensor-core flash attention (log2 softmax).
// QK^T: 3-term bf16 hi/lo. PV: 2-term, P single fp16 x V fp16 hi/lo.
// ---------------------------------------------------------------------------
#define FL_QBUF 16384
#define FL_KVST 32768
#define FL_SMEM (2 * FL_QBUF + 2 * FL_KVST)   // 96KB

__global__ __launch_bounds__(256) void flash_tc_kernel(
    const __nv_bfloat16* __restrict__ Qh, const __nv_bfloat16* __restrict__ Ql,
    const __nv_bfloat16* __restrict__ Kh, const __nv_bfloat16* __restrict__ Kl,
    const __half* __restrict__ Vh, const __half* __restrict__ Vl,
    __nv_bfloat16* __restrict__ Oh, __nv_bfloat16* __restrict__ Ol)
{
    extern __shared__ __align__(16) char smem[];
    const uint32_t base = smem_u32(smem);
    const int tid = threadIdx.x, wid = tid >> 5, lane = tid & 31;
    const int q0 = blockIdx.x * 128;
    const int bh = blockIdx.y;
    const size_t hb = (size_t)bh * S_ * HD_;

#pragma unroll
    for (int u = 0; u < 8; u++) {
        const int idx = tid + u * 256;
        const int bsel = idx >> 10;
        const int r = (idx >> 3) & 127;
        const int c = idx & 7;
        const __nv_bfloat16* src = (bsel ? Ql : Qh) + hb + (size_t)(q0 + r) * HD_ + c * 8;
        cp16(base + bsel * FL_QBUF + SWF(r, c), src);
    }
    cp_commit();

    auto loadkv = [&](int st, int kb) {
        const uint32_t sb = base + 2 * FL_QBUF + st * FL_KVST;
#pragma unroll
        for (int u = 0; u < 8; u++) {
            const int idx = tid + u * 256;
            const int b4 = idx >> 9;
            const int r = (idx >> 3) & 63;
            const int c = idx & 7;
            const void* g;
            if (b4 == 0)      g = Kh + hb + (size_t)(kb * 64 + r) * HD_ + c * 8;
            else if (b4 == 1) g = Kl + hb + (size_t)(kb * 64 + r) * HD_ + c * 8;
            else if (b4 == 2) g = Vh + hb + (size_t)(kb * 64 + r) * HD_ + c * 8;
            else              g = Vl + hb + (size_t)(kb * 64 + r) * HD_ + c * 8;
            cp16(sb + b4 * 8192 + SWF(r, c), g);
        }
        cp_commit();
    };
    loadkv(0, 0);
    loadkv(1, 1);

    float o[8][4];
#pragma unroll
    for (int nt = 0; nt < 8; nt++)
#pragma unroll
        for (int q = 0; q < 4; q++) o[nt][q] = 0.0f;
    float m0r = -1e30f, m1r = -1e30f, l0 = 0.0f, l1 = 0.0f;

    const int a_row = wid * 16 + (lane & 7) + ((lane >> 3) & 1) * 8;
    const int a_c   = lane >> 4;
    const int k_row = ((lane >> 4) & 1) * 8 + (lane & 7);
    const int k_c   = (lane >> 3) & 1;
    const int v_row = ((lane >> 3) & 1) * 8 + (lane & 7);
    const int v_c   = lane >> 4;

    const int NB = S_ / 64;   // 32
    for (int kb = 0; kb < NB; kb++) {
        if (kb < NB - 1) cp_wait1(); else cp_wait0();
        __syncthreads();
        const uint32_t stg = base + 2 * FL_QBUF + (kb & 1) * FL_KVST;

        float s[8][4];
#pragma unroll
        for (int nt = 0; nt < 8; nt++)
#pragma unroll
            for (int q = 0; q < 4; q++) s[nt][q] = 0.0f;

#pragma unroll
        for (int ks = 0; ks < 4; ks++) {
            uint32_t ah[4], al[4];
            ldsm4(ah, base +           SWF(a_row, 2 * ks + a_c));
            ldsm4(al, base + FL_QBUF + SWF(a_row, 2 * ks + a_c));
#pragma unroll
            for (int np = 0; np < 4; np++) {
                uint32_t bh4[4], bl4[4];
                ldsm4(bh4, stg +        SWF(np * 16 + k_row, 2 * ks + k_c));
                ldsm4(bl4, stg + 8192 + SWF(np * 16 + k_row, 2 * ks + k_c));
#pragma unroll
                for (int hh = 0; hh < 2; hh++) {
                    float* sc = s[2 * np + hh];
                    mma16816(sc, ah, bh4[2 * hh], bh4[2 * hh + 1]);
                    mma16816(sc, ah, bl4[2 * hh], bl4[2 * hh + 1]);
                    mma16816(sc, al, bh4[2 * hh], bh4[2 * hh + 1]);
                }
            }
        }

        float mx0 = -1e30f, mx1 = -1e30f;
#pragma unroll
        for (int nt = 0; nt < 8; nt++) {
            mx0 = fmaxf(mx0, fmaxf(s[nt][0], s[nt][1]));
            mx1 = fmaxf(mx1, fmaxf(s[nt][2], s[nt][3]));
        }
        mx0 = fmaxf(mx0, __shfl_xor_sync(0xffffffffu, mx0, 1));
        mx0 = fmaxf(mx0, __shfl_xor_sync(0xffffffffu, mx0, 2));
        mx1 = fmaxf(mx1, __shfl_xor_sync(0xffffffffu, mx1, 1));
        mx1 = fmaxf(mx1, __shfl_xor_sync(0xffffffffu, mx1, 2));
        const float mn0 = fmaxf(m0r, mx0);
        const float mn1 = fmaxf(m1r, mx1);
        const float al0 = ex2f(m0r - mn0);
        const float al1 = ex2f(m1r - mn1);
        m0r = mn0; m1r = mn1;

        float sum0 = 0.0f, sum1 = 0.0f;
#pragma unroll
        for (int nt = 0; nt < 8; nt++) {
            s[nt][0] = ex2f(s[nt][0] - mn0);
            s[nt][1] = ex2f(s[nt][1] - mn0);
            s[nt][2] = ex2f(s[nt][2] - mn1);
            s[nt][3] = ex2f(s[nt][3] - mn1);
            sum0 += s[nt][0] + s[nt][1];
            sum1 += s[nt][2] + s[nt][3];
        }
        sum0 += __shfl_xor_sync(0xffffffffu, sum0, 1);
        sum0 += __shfl_xor_sync(0xffffffffu, sum0, 2);
        sum1 += __shfl_xor_sync(0xffffffffu, sum1, 1);
        sum1 += __shfl_xor_sync(0xffffffffu, sum1, 2);
        l0 = l0 * al0 + sum0;
        l1 = l1 * al1 + sum1;
#pragma unroll
        for (int nt = 0; nt < 8; nt++) {
            o[nt][0] *= al0; o[nt][1] *= al0;
            o[nt][2] *= al1; o[nt][3] *= al1;
        }

        // pack P as single fp16 fragments
        uint32_t ap[4][4];
#pragma unroll
        for (int kc = 0; kc < 4; kc++) {
            ap[kc][0] = pack_f16(s[2 * kc][0],     s[2 * kc][1]);
            ap[kc][1] = pack_f16(s[2 * kc][2],     s[2 * kc][3]);
            ap[kc][2] = pack_f16(s[2 * kc + 1][0], s[2 * kc + 1][1]);
            ap[kc][3] = pack_f16(s[2 * kc + 1][2], s[2 * kc + 1][3]);
        }

        // O += P V  (2 terms: P x Vh + P x Vl, fp16 mma)
        const uint32_t vhb = stg + 16384, vlb = stg + 24576;
#pragma unroll
        for (int dp = 0; dp < 4; dp++) {
#pragma unroll
            for (int kc = 0; kc < 4; kc++) {
                uint32_t vh4[4], vl4[4];
                ldsm4t(vh4, vhb + SWF(kc * 16 + v_row, 2 * dp + v_c));
                ldsm4t(vl4, vlb + SWF(kc * 16 + v_row, 2 * dp + v_c));
                mma16816h(o[2 * dp],     ap[kc], vh4[0], vh4[1]);
                mma16816h(o[2 * dp],     ap[kc], vl4[0], vl4[1]);
                mma16816h(o[2 * dp + 1], ap[kc], vh4[2], vh4[3]);
                mma16816h(o[2 * dp + 1], ap[kc], vl4[2], vl4[3]);
            }
        }
        __syncthreads();
        if (kb + 2 < NB) loadkv(kb & 1, kb + 2);
    }

    const float inv0 = 1.0f / l0, inv1 = 1.0f / l1;
    const int h = bh & (H_ - 1);
    const int bb = bh >> 4;
    const int r0 = q0 + wid * 16 + (lane >> 2);
    const int r1 = r0 + 8;
#pragma unroll
    for (int nt = 0; nt < 8; nt++) {
        const int gd = h * 64 + nt * 8 + (lane & 3) * 2;
        const size_t i0 = ((size_t)bb * S_ + r0) * D_ + gd;
        const size_t i1 = ((size_t)bb * S_ + r1) * D_ + gd;
        float lx, ly;
        *(uint32_t*)&Oh[i0] = pack_bf16_hi(o[nt][0] * inv0, o[nt][1] * inv0, lx, ly);
        *(uint32_t*)&Ol[i0] = pack_bf16(lx, ly);
        *(uint32_t*)&Oh[i1] = pack_bf16_hi(o[nt][2] * inv1, o[nt][3] * inv1, lx, ly);
        *(uint32_t*)&Ol[i1] = pack_bf16(lx, ly);
    }
}

// ---------------------------------------------------------------------------

extern "C" void kernel_launch(void* const* d_in, const int* in_sizes, int n_in,
                              void* d_out, int out_size)
{
    (void)in_sizes; (void)n_in; (void)out_size;
    const float* x  = (const float*)d_in[0];
    const float* Wq = (const float*)d_in[1];
    const float* bq = (const float*)d_in[2];
    const float* Wk = (const float*)d_in[3];
    const float* bk = (const float*)d_in[4];
    const float* Wv = (const float*)d_in[5];
    const float* bv = (const float*)d_in[6];
    const float* Wo = (const float*)d_in[7];
    const float* bo = (const float*)d_in[8];
    float* out = (float*)d_out;

    __nv_bfloat16 *xhi, *xlo, *ahi, *alo, *wthi, *wtlo;
    __nv_bfloat16 *qh, *ql, *kh, *kl;
    __half *vh, *vl;
    cudaGetSymbolAddress((void**)&xhi,  g_xhi);
    cudaGetSymbolAddress((void**)&xlo,  g_xlo);
    cudaGetSymbolAddress((void**)&ahi,  g_ahi);
    cudaGetSymbolAddress((void**)&alo,  g_alo);
    cudaGetSymbolAddress((void**)&wthi, g_wthi);
    cudaGetSymbolAddress((void**)&wtlo, g_wtlo);
    cudaGetSymbolAddress((void**)&qh,   g_qh);
    cudaGetSymbolAddress((void**)&ql,   g_ql);
    cudaGetSymbolAddress((void**)&kh,   g_kh);
    cudaGetSymbolAddress((void**)&kl,   g_kl);
    cudaGetSymbolAddress((void**)&vh,   g_vh);
    cudaGetSymbolAddress((void**)&vl,   g_vl);

    cudaFuncSetAttribute(gemm_mma_kernel<1>,
        cudaFuncAttributeMaxDynamicSharedMemorySize, GEMM_SMEM);
    cudaFuncSetAttribute(gemm_mma_kernel<0>,
        cudaFuncAttributeMaxDynamicSharedMemorySize, GEMM_SMEM);
    cudaFuncSetAttribute(flash_tc_kernel,
        cudaFuncAttributeMaxDynamicSharedMemorySize, FL_SMEM);

    const int NEL = M_ * D_;
    split_kernel<<<NEL / 4096, 256>>>(x, xhi, xlo, NEL);
    transW_kernel<<<dim3(16, 32, 4), 256>>>(Wq, Wk, Wv, Wo, wthi, wtlo);

    gemm_mma_kernel<1><<<dim3(8, 32, 3), 256, GEMM_SMEM>>>(
        xhi, xlo, wthi, wtlo, bq, bk, bv,
        nullptr, qh, ql, kh, kl, vh, vl);

    flash_tc_kernel<<<dim3(S_ / 128, B_ * H_), 256, FL_SMEM>>>(
        qh, ql, kh, kl, vh, vl, ahi, alo);

    gemm_mma_kernel<0><<<dim3(8, 32, 1), 256, GEMM_SMEM>>>(
        ahi, alo, wthi + (size_t)3 * D_ * D_, wtlo + (size_t)3 * D_ * D_,
        bo, bo, bo, out, nullptr, nullptr, nullptr, nullptr, nullptr, nullptr);
}